// round 14
// baseline (speedup 1.0000x reference)
#include <cuda_runtime.h>
#include <cuda_bf16.h>
#include <cstdint>

#define NN 50000
#define EE 800000
#define DD 128
#define FF 16
#define LL 5

typedef unsigned long long ull;
typedef unsigned short u16;

// ===================== fp32 packed-FMA helpers =====================
__device__ __forceinline__ ull ffma2(ull a, ull b, ull c) {
    ull d;
    asm("fma.rn.f32x2 %0,%1,%2,%3;" : "=l"(d) : "l"(a), "l"(b), "l"(c));
    return d;
}
__device__ __forceinline__ ull pack2(float lo, float hi) {
    ull r;
    asm("mov.b64 %0,{%1,%2};" : "=l"(r) : "f"(lo), "f"(hi));
    return r;
}
__device__ __forceinline__ void unpack2(ull v, float& lo, float& hi) {
    asm("mov.b64 {%0,%1},%2;" : "=f"(lo), "=f"(hi) : "l"(v));
}

__device__ __forceinline__ uint32_t smem_u32(const void* p) {
    uint32_t a;
    asm("{ .reg .u64 t; cvta.to.shared.u64 t, %1; cvt.u32.u64 %0, t; }" : "=r"(a) : "l"(p));
    return a;
}

// ===================== mma.sync helpers (baseline PTX) =====================
__device__ __forceinline__ void ldsm4(uint32_t* r, uint32_t addr) {
    asm volatile("ldmatrix.sync.aligned.m8n8.x4.shared.b16 {%0,%1,%2,%3}, [%4];"
                 : "=r"(r[0]), "=r"(r[1]), "=r"(r[2]), "=r"(r[3]) : "r"(addr));
}
__device__ __forceinline__ void mma_bf16(float* d, const uint32_t* a, const uint32_t* b) {
    asm volatile("mma.sync.aligned.m16n8k16.row.col.f32.bf16.bf16.f32 "
                 "{%0,%1,%2,%3},{%4,%5,%6,%7},{%8,%9},{%0,%1,%2,%3};"
                 : "+f"(d[0]), "+f"(d[1]), "+f"(d[2]), "+f"(d[3])
                 : "r"(a[0]), "r"(a[1]), "r"(a[2]), "r"(a[3]), "r"(b[0]), "r"(b[1]));
}

#define TSTRIDE 136
#define TILE_U16 (128 * TSTRIDE)
#define GEMM_SMEM (4 * TILE_U16 * 2)    // 139264 B dynamic (R7-proven layout)

// ===================== device scratch =====================
__device__ float g_h[NN * DD];
__device__ u16   g_z0h[NN * DD];
__device__ u16   g_z0l[NN * DD];
__device__ float g_t[NN * 2 * DD];
__device__ u16   g_t2h[NN * 2 * DD];
__device__ u16   g_t2l[NN * 2 * DD];
__device__ float g_z2[NN * DD];
__device__ u16   g_w1t_h[LL * 256 * 128], g_w1t_l[LL * 256 * 128];
__device__ u16   g_w2t_h[LL * 128 * 256], g_w2t_l[LL * 128 * 256];
__device__ int   g_cnt[NN];
__device__ int   g_rowptr[NN + 1];
__device__ int   g_fill[NN];
__device__ int2  g_sorted[EE];
__device__ int   g_part[200], g_partx[200];
__device__ float g_sum1[2 * DD], g_sq1[2 * DD];
__device__ float g_sum2[DD], g_sq2[DD];

// ===================== bf16 split helpers =====================
__device__ __forceinline__ void split4(float a, float b, float c, float d, uint2& hi, uint2& lo) {
    __nv_bfloat16 h0 = __float2bfloat16(a), h1 = __float2bfloat16(b);
    __nv_bfloat16 h2 = __float2bfloat16(c), h3 = __float2bfloat16(d);
    __nv_bfloat16 l0 = __float2bfloat16(a - __bfloat162float(h0));
    __nv_bfloat16 l1 = __float2bfloat16(b - __bfloat162float(h1));
    __nv_bfloat16 l2 = __float2bfloat16(c - __bfloat162float(h2));
    __nv_bfloat16 l3 = __float2bfloat16(d - __bfloat162float(h3));
    hi.x = (uint32_t)__bfloat16_as_ushort(h0) | ((uint32_t)__bfloat16_as_ushort(h1) << 16);
    hi.y = (uint32_t)__bfloat16_as_ushort(h2) | ((uint32_t)__bfloat16_as_ushort(h3) << 16);
    lo.x = (uint32_t)__bfloat16_as_ushort(l0) | ((uint32_t)__bfloat16_as_ushort(l1) << 16);
    lo.y = (uint32_t)__bfloat16_as_ushort(l2) | ((uint32_t)__bfloat16_as_ushort(l3) << 16);
}
__device__ __forceinline__ void split2(float a, float b, uint32_t& hi, uint32_t& lo) {
    __nv_bfloat16 h0 = __float2bfloat16(a), h1 = __float2bfloat16(b);
    __nv_bfloat16 l0 = __float2bfloat16(a - __bfloat162float(h0));
    __nv_bfloat16 l1 = __float2bfloat16(b - __bfloat162float(h1));
    hi = (uint32_t)__bfloat16_as_ushort(h0) | ((uint32_t)__bfloat16_as_ushort(h1) << 16);
    lo = (uint32_t)__bfloat16_as_ushort(l0) | ((uint32_t)__bfloat16_as_ushort(l1) << 16);
}

// ===================== init =====================
__global__ void k_init() {
    int i = blockIdx.x * blockDim.x + threadIdx.x;
    if (i < NN) g_cnt[i] = 0;
    if (i < 2 * DD) { g_sum1[i] = 0.f; g_sq1[i] = 0.f; }
    if (i < DD)     { g_sum2[i] = 0.f; g_sq2[i] = 0.f; }
}

// ===================== weight transpose + bf16 split =====================
__global__ void k_wconv(const float* __restrict__ W1, const float* __restrict__ W2) {
    int i = blockIdx.x * blockDim.x + threadIdx.x;
    if (i < LL * 32768) {
        int l = i >> 15, r = i & 32767, n = r >> 7, k = r & 127;
        float w = W1[(l << 15) + k * 256 + n];
        __nv_bfloat16 h = __float2bfloat16(w);
        __nv_bfloat16 lo = __float2bfloat16(w - __bfloat162float(h));
        g_w1t_h[i] = __bfloat16_as_ushort(h);
        g_w1t_l[i] = __bfloat16_as_ushort(lo);
    } else if (i < 2 * LL * 32768) {
        int j = i - LL * 32768;
        int l = j >> 15, r = j & 32767, n = r >> 8, k = r & 255;
        float w = W2[(l << 15) + k * 128 + n];
        __nv_bfloat16 h = __float2bfloat16(w);
        __nv_bfloat16 lo = __float2bfloat16(w - __bfloat162float(h));
        g_w2t_h[j] = __bfloat16_as_ushort(h);
        g_w2t_l[j] = __bfloat16_as_ushort(lo);
    }
}

// ===================== CSR build =====================
__global__ void k_hist(const int* __restrict__ ei) {
    int e = blockIdx.x * blockDim.x + threadIdx.x;
    if (e < EE) atomicAdd(&g_cnt[ei[EE + e]], 1);
}

__global__ void k_scanA() {
    __shared__ int red[8];
    int tid = threadIdx.x, lid = tid & 31, wid = tid >> 5;
    int i = blockIdx.x * 256 + tid;
    int v = (i < NN) ? g_cnt[i] : 0;
    #pragma unroll
    for (int o = 16; o >= 1; o >>= 1) v += __shfl_down_sync(0xffffffffu, v, o);
    if (lid == 0) red[wid] = v;
    __syncthreads();
    if (tid < 8) {
        int s = red[tid];
        #pragma unroll
        for (int o = 4; o >= 1; o >>= 1) s += __shfl_down_sync(0xffu, s, o);
        if (tid == 0) g_part[blockIdx.x] = s;
    }
}

__global__ void k_scanB(int nb) {
    __shared__ int ws[8];
    int tid = threadIdx.x, lid = tid & 31, wid = tid >> 5;
    int v = (tid < nb) ? g_part[tid] : 0;
    int x = v;
    #pragma unroll
    for (int o = 1; o < 32; o <<= 1) {
        int t = __shfl_up_sync(0xffffffffu, x, o);
        if (lid >= o) x += t;
    }
    if (lid == 31) ws[wid] = x;
    __syncthreads();
    if (wid == 0 && lid < 8) {
        int s = ws[lid], y = s;
        #pragma unroll
        for (int o = 1; o < 8; o <<= 1) {
            int t = __shfl_up_sync(0xffu, y, o);
            if (lid >= o) y += t;
        }
        ws[lid] = y - s;
    }
    __syncthreads();
    int excl = ws[wid] + x - v;
    if (tid < nb) g_partx[tid] = excl;
    if (tid == nb - 1) g_rowptr[NN] = excl + v;
}

__global__ void k_scanC() {
    __shared__ int ws[8];
    int tid = threadIdx.x, lid = tid & 31, wid = tid >> 5;
    int i = blockIdx.x * 256 + tid;
    int v = (i < NN) ? g_cnt[i] : 0;
    int x = v;
    #pragma unroll
    for (int o = 1; o < 32; o <<= 1) {
        int t = __shfl_up_sync(0xffffffffu, x, o);
        if (lid >= o) x += t;
    }
    if (lid == 31) ws[wid] = x;
    __syncthreads();
    if (wid == 0 && lid < 8) {
        int s = ws[lid], y = s;
        #pragma unroll
        for (int o = 1; o < 8; o <<= 1) {
            int t = __shfl_up_sync(0xffu, y, o);
            if (lid >= o) y += t;
        }
        ws[lid] = y - s;
    }
    __syncthreads();
    int excl = g_partx[blockIdx.x] + ws[wid] + x - v;
    if (i < NN) { g_rowptr[i] = excl; g_fill[i] = excl; }
}

__global__ void k_scatter(const int* __restrict__ ei) {
    int e = blockIdx.x * blockDim.x + threadIdx.x;
    if (e < EE) {
        int d = ei[EE + e];
        int pos = atomicAdd(&g_fill[d], 1);
        g_sorted[pos] = make_int2(ei[e], e);
    }
}

// ===================== node encoder =====================
__global__ void k_node_enc(const float* __restrict__ x, const float* __restrict__ Wn,
                           const float* __restrict__ bn) {
    __shared__ float Ws[FF * DD];
    for (int i = threadIdx.x; i < FF * DD; i += blockDim.x) Ws[i] = Wn[i];
    __syncthreads();
    int lane = threadIdx.x & 31;
    int warp = (blockIdx.x * blockDim.x + threadIdx.x) >> 5;
    int nw = (gridDim.x * blockDim.x) >> 5;
    int c0 = lane * 4;
    ull wp[8][4];
    #pragma unroll
    for (int j = 0; j < 8; j++)
        #pragma unroll
        for (int ci = 0; ci < 4; ci++)
            wp[j][ci] = pack2(Ws[(2 * j) * DD + c0 + ci], Ws[(2 * j + 1) * DD + c0 + ci]);
    ull bias2[4];
    #pragma unroll
    for (int ci = 0; ci < 4; ci++) bias2[ci] = pack2(bn[c0 + ci], 0.f);
    for (int n = warp; n < NN; n += nw) {
        const float4* xr = (const float4*)(x + (size_t)n * FF);
        float4 e0 = xr[0], e1 = xr[1], e2 = xr[2], e3 = xr[3];
        ull xp[8] = { pack2(e0.x, e0.y), pack2(e0.z, e0.w), pack2(e1.x, e1.y), pack2(e1.z, e1.w),
                      pack2(e2.x, e2.y), pack2(e2.z, e2.w), pack2(e3.x, e3.y), pack2(e3.z, e3.w) };
        ull a0 = bias2[0], a1 = bias2[1], a2 = bias2[2], a3 = bias2[3];
        #pragma unroll
        for (int j = 0; j < 8; j++) {
            a0 = ffma2(xp[j], wp[j][0], a0);
            a1 = ffma2(xp[j], wp[j][1], a1);
            a2 = ffma2(xp[j], wp[j][2], a2);
            a3 = ffma2(xp[j], wp[j][3], a3);
        }
        float l0, h0, l1, h1, l2, h2, l3, h3;
        unpack2(a0, l0, h0); unpack2(a1, l1, h1);
        unpack2(a2, l2, h2); unpack2(a3, l3, h3);
        *(float4*)&g_h[(size_t)n * DD + c0] = make_float4(l0 + h0, l1 + h1, l2 + h2, l3 + h3);
    }
}

// ===================== fused edge-encode + gather + aggregate =====================
// 2 warps per node: warp parity picks a fixed 64-column half; each lane owns 2 columns.
// Halves per-lane weight registers (16 ull) -> higher occupancy -> more gathers in flight.
// Inner loop structure (2-edge unroll, broadcast pack, CSR order) preserved from R3.
__global__ void k_agg(const float* __restrict__ ea, const float* __restrict__ We,
                      const float* __restrict__ be, const float* __restrict__ epsv, int layer) {
    __shared__ float Ws[FF * DD];
    for (int i = threadIdx.x; i < FF * DD; i += blockDim.x) Ws[i] = We[layer * FF * DD + i];
    if (blockIdx.x == 0 && threadIdx.x < DD) { g_sum2[threadIdx.x] = 0.f; g_sq2[threadIdx.x] = 0.f; }
    __syncthreads();
    int lane = threadIdx.x & 31;
    int warp = (blockIdx.x * blockDim.x + threadIdx.x) >> 5;
    int nw = (gridDim.x * blockDim.x) >> 5;
    int half = warp & 1;
    int nstep = nw >> 1;
    int c0 = half * 64 + lane * 2;
    ull w2[FF];
    #pragma unroll
    for (int f = 0; f < FF; f++)
        w2[f] = *(const ull*)&Ws[f * DD + c0];
    ull b2v = *(const ull*)&be[layer * DD + c0];
    float eps1 = 1.0f + epsv[layer];

    for (int n = warp >> 1; n < NN; n += nstep) {
        int p0 = g_rowptr[n], p1 = g_rowptr[n + 1];
        float ax = 0.f, ay = 0.f;
        int p = p0;
        for (; p + 1 < p1; p += 2) {
            int2 seA = g_sorted[p];
            int2 seB = g_sorted[p + 1];
            const float4* erA = (const float4*)(ea + (size_t)seA.y * FF);
            const float4* erB = (const float4*)(ea + (size_t)seB.y * FF);
            float xaA[16], xaB[16];
            *(float4*)&xaA[0] = erA[0]; *(float4*)&xaA[4] = erA[1];
            *(float4*)&xaA[8] = erA[2]; *(float4*)&xaA[12] = erA[3];
            *(float4*)&xaB[0] = erB[0]; *(float4*)&xaB[4] = erB[1];
            *(float4*)&xaB[8] = erB[2]; *(float4*)&xaB[12] = erB[3];
            float2 hvA = *(const float2*)&g_h[(size_t)seA.x * DD + c0];
            float2 hvB = *(const float2*)&g_h[(size_t)seB.x * DD + c0];
            ull mA = b2v, mB = b2v;
            #pragma unroll
            for (int f = 0; f < FF; f++) {
                mA = ffma2(pack2(xaA[f], xaA[f]), w2[f], mA);
                mB = ffma2(pack2(xaB[f], xaB[f]), w2[f], mB);
            }
            float a0, a1, b0, b1f;
            unpack2(mA, a0, a1);
            unpack2(mB, b0, b1f);
            ax += fmaxf(a0 + hvA.x, 0.f) + fmaxf(b0 + hvB.x, 0.f);
            ay += fmaxf(a1 + hvA.y, 0.f) + fmaxf(b1f + hvB.y, 0.f);
        }
        if (p < p1) {
            int2 se = g_sorted[p];
            const float4* er = (const float4*)(ea + (size_t)se.y * FF);
            float xa[16];
            *(float4*)&xa[0] = er[0]; *(float4*)&xa[4] = er[1];
            *(float4*)&xa[8] = er[2]; *(float4*)&xa[12] = er[3];
            float2 hv = *(const float2*)&g_h[(size_t)se.x * DD + c0];
            ull m = b2v;
            #pragma unroll
            for (int f = 0; f < FF; f++)
                m = ffma2(pack2(xa[f], xa[f]), w2[f], m);
            float m0, m1;
            unpack2(m, m0, m1);
            ax += fmaxf(m0 + hv.x, 0.f);
            ay += fmaxf(m1 + hv.y, 0.f);
        }
        float2 hs = *(const float2*)&g_h[(size_t)n * DD + c0];
        float o0 = fmaf(eps1, hs.x, ax), o1 = fmaf(eps1, hs.y, ay);
        uint32_t hi, lo;
        split2(o0, o1, hi, lo);
        *(uint32_t*)&g_z0h[(size_t)n * DD + c0] = hi;
        *(uint32_t*)&g_z0l[(size_t)n * DD + c0] = lo;
    }
}

// ===================== stage 128x128 bf16 tile into padded smem (256 threads) =====================
__device__ __forceinline__ void stage_tile(u16* s, const uint4* src, int stride_u4,
                                           int off_u4, int vr, int tid) {
    #pragma unroll
    for (int j = 0; j < 8; j++) {
        int idx = tid + j * 256;
        int r = idx >> 4, q = idx & 15;
        uint4 v = make_uint4(0u, 0u, 0u, 0u);
        if (r < vr) v = src[(size_t)r * stride_u4 + off_u4 + q];
        *(uint4*)&s[r * TSTRIDE + q * 8] = v;
    }
}

// ===================== dual-A mma pass: (Ah·B + Al·B) with B fragments loaded ONCE =====================
__device__ __forceinline__ void gemm_pass_dual(uint32_t sAh, uint32_t sAl, uint32_t sB,
                                               int lane, int wm, int wn, float acc[2][8][4]) {
    uint32_t a_off = ((uint32_t)((wm * 32 + (lane & 15)) * TSTRIDE + ((lane >> 4) << 3)) << 1);
    uint32_t a_baseH = sAh + a_off;
    uint32_t a_baseL = sAl + a_off;
    int noff = (lane & 7) + ((lane & 16) >> 1);
    int koff = (lane & 8) ? 8 : 0;
    #pragma unroll
    for (int ks = 0; ks < 8; ks++) {
        int k0 = ks * 16;
        uint32_t bF[8][2];
        #pragma unroll
        for (int p = 0; p < 4; p++) {
            uint32_t r[4];
            uint32_t b_addr = sB + ((uint32_t)((wn * 64 + p * 16 + noff) * TSTRIDE + k0 + koff) << 1);
            ldsm4(r, b_addr);
            bF[2 * p][0] = r[0]; bF[2 * p][1] = r[1];
            bF[2 * p + 1][0] = r[2]; bF[2 * p + 1][1] = r[3];
        }
        uint32_t aH[2][4], aL[2][4];
        ldsm4(aH[0], a_baseH + (k0 << 1));
        ldsm4(aH[1], a_baseH + ((16 * TSTRIDE + k0) << 1));
        ldsm4(aL[0], a_baseL + (k0 << 1));
        ldsm4(aL[1], a_baseL + ((16 * TSTRIDE + k0) << 1));
        #pragma unroll
        for (int mt = 0; mt < 2; mt++)
            #pragma unroll
            for (int nt = 0; nt < 8; nt++)
                mma_bf16(acc[mt][nt], aH[mt], bF[nt]);
        #pragma unroll
        for (int mt = 0; mt < 2; mt++)
            #pragma unroll
            for (int nt = 0; nt < 8; nt++)
                mma_bf16(acc[mt][nt], aL[mt], bF[nt]);
    }
}

// ===================== single-A mma pass (Ah·Bl) =====================
__device__ __forceinline__ void gemm_pass(uint32_t sA, uint32_t sB, int lane, int wm, int wn,
                                          float acc[2][8][4]) {
    uint32_t a_base = sA + ((uint32_t)((wm * 32 + (lane & 15)) * TSTRIDE + ((lane >> 4) << 3)) << 1);
    int noff = (lane & 7) + ((lane & 16) >> 1);
    int koff = (lane & 8) ? 8 : 0;
    #pragma unroll
    for (int ks = 0; ks < 8; ks++) {
        int k0 = ks * 16;
        uint32_t aF[2][4];
        ldsm4(aF[0], a_base + (k0 << 1));
        ldsm4(aF[1], a_base + ((16 * TSTRIDE + k0) << 1));
        uint32_t bF[8][2];
        #pragma unroll
        for (int p = 0; p < 4; p++) {
            uint32_t r[4];
            uint32_t b_addr = sB + ((uint32_t)((wn * 64 + p * 16 + noff) * TSTRIDE + k0 + koff) << 1);
            ldsm4(r, b_addr);
            bF[2 * p][0] = r[0]; bF[2 * p][1] = r[1];
            bF[2 * p + 1][0] = r[2]; bF[2 * p + 1][1] = r[3];
        }
        #pragma unroll
        for (int mt = 0; mt < 2; mt++)
            #pragma unroll
            for (int nt = 0; nt < 8; nt++)
                mma_bf16(acc[mt][nt], aF[mt], bF[nt]);
    }
}

// ===================== GEMM1: t[N,256] = z0 @ W1 + b1 (+ column stats) =====================
__global__ void __launch_bounds__(256) k_gemm1(int layer, const float* __restrict__ b1) {
    extern __shared__ u16 sm[];
    u16* sAh = sm;
    u16* sAl = sAh + TILE_U16;
    u16* sBh = sAl + TILE_U16;
    u16* sBl = sBh + TILE_U16;
    int tid = threadIdx.x, lane = tid & 31, w = tid >> 5;
    int wm = w >> 1, wn = w & 1;
    int rbase = blockIdx.x * 128, nblk = blockIdx.y;
    int vr = NN - rbase; if (vr > 128) vr = 128;

    stage_tile(sAh, (const uint4*)(g_z0h + (size_t)rbase * DD), 16, 0, vr, tid);
    stage_tile(sAl, (const uint4*)(g_z0l + (size_t)rbase * DD), 16, 0, vr, tid);
    const uint4* Bh = (const uint4*)(g_w1t_h + (size_t)layer * 32768 + (size_t)nblk * 128 * 128);
    const uint4* Bl = (const uint4*)(g_w1t_l + (size_t)layer * 32768 + (size_t)nblk * 128 * 128);
    stage_tile(sBh, Bh, 16, 0, 128, tid);
    stage_tile(sBl, Bl, 16, 0, 128, tid);
    __syncthreads();

    float acc[2][8][4];
    #pragma unroll
    for (int mt = 0; mt < 2; mt++)
        #pragma unroll
        for (int nt = 0; nt < 8; nt++)
            #pragma unroll
            for (int i = 0; i < 4; i++) acc[mt][nt][i] = 0.f;

    uint32_t uAh = smem_u32(sAh), uAl = smem_u32(sAl);
    uint32_t uBh = smem_u32(sBh), uBl = smem_u32(sBl);
    gemm_pass_dual(uAh, uAl, uBh, lane, wm, wn, acc);
    gemm_pass(uAh, uBl, lane, wm, wn, acc);

    int colb = nblk * 128 + wn * 64;
    int r0 = rbase + wm * 32 + (lane >> 2);
    float s[16], q[16];
    #pragma unroll
    for (int nt = 0; nt < 8; nt++) {
        int c = colb + nt * 8 + 2 * (lane & 3);
        float bx = __ldg(&b1[c]), by = __ldg(&b1[c + 1]);
        float v0 = acc[0][nt][0] + bx, v1 = acc[0][nt][1] + by;
        float v2 = acc[0][nt][2] + bx, v3 = acc[0][nt][3] + by;
        float u0 = acc[1][nt][0] + bx, u1 = acc[1][nt][1] + by;
        float u2 = acc[1][nt][2] + bx, u3 = acc[1][nt][3] + by;
        bool oa = r0 < NN, ob = r0 + 8 < NN, oc = r0 + 16 < NN, od = r0 + 24 < NN;
        if (oa) *(float2*)&g_t[(size_t)r0 * 256 + c]        = make_float2(v0, v1);
        if (ob) *(float2*)&g_t[(size_t)(r0 + 8) * 256 + c]  = make_float2(v2, v3);
        if (oc) *(float2*)&g_t[(size_t)(r0 + 16) * 256 + c] = make_float2(u0, u1);
        if (od) *(float2*)&g_t[(size_t)(r0 + 24) * 256 + c] = make_float2(u2, u3);
        float s0 = 0.f, s1 = 0.f, q0 = 0.f, q1 = 0.f;
        if (oa) { s0 += v0; s1 += v1; q0 += v0 * v0; q1 += v1 * v1; }
        if (ob) { s0 += v2; s1 += v3; q0 += v2 * v2; q1 += v3 * v3; }
        if (oc) { s0 += u0; s1 += u1; q0 += u0 * u0; q1 += u1 * u1; }
        if (od) { s0 += u2; s1 += u3; q0 += u2 * u2; q1 += u3 * u3; }
        s[2 * nt] = s0; s[2 * nt + 1] = s1; q[2 * nt] = q0; q[2 * nt + 1] = q1;
    }
    #pragma unroll
    for (int off = 16; off >= 4; off >>= 1) {
        #pragma unroll
        for (int i = 0; i < 16; i++) {
            s[i] += __shfl_down_sync(0xffffffffu, s[i], off);
            q[i] += __shfl_down_sync(0xffffffffu, q[i], off);
        }
    }
    if (lane < 4) {
        #pragma unroll
        for (int nt = 0; nt < 8; nt++) {
            int c = colb + nt * 8 + 2 * lane;
            atomicAdd(&g_sum1[c], s[2 * nt]);
            atomicAdd(&g_sum1[c + 1], s[2 * nt + 1]);
            atomicAdd(&g_sq1[c], q[2 * nt]);
            atomicAdd(&g_sq1[c + 1], q[2 * nt + 1]);
        }
    }
}

// ===================== conv2 (BN1 finalize fused): t2 = relu(BN1(t)) as bf16 hi/lo =====================
__global__ void k_conv2(const float* __restrict__ g1, const float* __restrict__ beta1) {
    __shared__ float s_sc[2 * DD], s_sh[2 * DD];
    int tid = threadIdx.x;
    {
        const float invN = 1.0f / (float)NN;
        float m = g_sum1[tid] * invN;
        float v = g_sq1[tid] * invN - m * m;
        float sc = g1[tid] * rsqrtf(v + 1e-5f);
        s_sc[tid] = sc;
        s_sh[tid] = beta1[tid] - m * sc;
    }
    __syncthreads();
    for (int i = blockIdx.x * blockDim.x + tid; i < NN * 64; i += gridDim.x * blockDim.x) {
        int c4 = i & 63;
        float4 t = ((const float4*)g_t)[i];
        float4 sc = ((const float4*)s_sc)[c4];
        float4 sh = ((const float4*)s_sh)[c4];
        float v0 = fmaxf(fmaf(t.x, sc.x, sh.x), 0.f);
        float v1 = fmaxf(fmaf(t.y, sc.y, sh.y), 0.f);
        float v2 = fmaxf(fmaf(t.z, sc.z, sh.z), 0.f);
        float v3 = fmaxf(fmaf(t.w, sc.w, sh.w), 0.f);
        uint2 hi, lo;
        split4(v0, v1, v2, v3, hi, lo);
        ((uint2*)g_t2h)[i] = hi;
        ((uint2*)g_t2l)[i] = lo;
    }
}

// ===================== GEMM2: z2[N,128] = t2 @ W2 + b2 (K=256, 2 chunks; + stats) =====================
__global__ void __launch_bounds__(256) k_gemm2(int layer, const float* __restrict__ b2) {
    extern __shared__ u16 sm[];
    u16* sAh = sm;
    u16* sAl = sAh + TILE_U16;
    u16* sBh = sAl + TILE_U16;
    u16* sBl = sBh + TILE_U16;
    int tid = threadIdx.x, lane = tid & 31, w = tid >> 5;
    int wm = w >> 1, wn = w & 1;
    int rbase = blockIdx.x * 128;
    int vr = NN - rbase; if (vr > 128) vr = 128;

    const uint4* Ah = (const uint4*)(g_t2h + (size_t)rbase * 256);
    const uint4* Al = (const uint4*)(g_t2l + (size_t)rbase * 256);
    const uint4* Bh = (const uint4*)(g_w2t_h + (size_t)layer * 32768);
    const uint4* Bl = (const uint4*)(g_w2t_l + (size_t)layer * 32768);

    float acc[2][8][4];
    #pragma unroll
    for (int mt = 0; mt < 2; mt++)
        #pragma unroll
        for (int nt = 0; nt < 8; nt++)
            #pragma unroll
            for (int i = 0; i < 4; i++) acc[mt][nt][i] = 0.f;

    uint32_t uAh = smem_u32(sAh), uAl = smem_u32(sAl);
    uint32_t uBh = smem_u32(sBh), uBl = smem_u32(sBl);

    #pragma unroll
    for (int c = 0; c < 2; c++) {
        if (c) __syncthreads();
        stage_tile(sAh, Ah, 32, c * 16, vr, tid);
        stage_tile(sAl, Al, 32, c * 16, vr, tid);
        stage_tile(sBh, Bh, 32, c * 16, 128, tid);
        stage_tile(sBl, Bl, 32, c * 16, 128, tid);
        __syncthreads();
        gemm_pass_dual(uAh, uAl, uBh, lane, wm, wn, acc);
        gemm_pass(uAh, uBl, lane, wm, wn, acc);
    }

    int colb = wn * 64;
    int r0 = rbase + wm * 32 + (lane >> 2);
    float s[16], q[16];
    #pragma unroll
    for (int nt = 0; nt < 8; nt++) {
        int c = colb + nt * 8 + 2 * (lane & 3);
        float bx = __ldg(&b2[c]), by = __ldg(&b2[c + 1]);
        float v0 = acc[0][nt][0] + bx, v1 = acc[0][nt][1] + by;
        float v2 = acc[0][nt][2] + bx, v3 = acc[0][nt][3] + by;
        float u0 = acc[1][nt][0] + bx, u1 = acc[1][nt][1] + by;
        float u2 = acc[1][nt][2] + bx, u3 = acc[1][nt][3] + by;
        bool oa = r0 < NN, ob = r0 + 8 < NN, oc = r0 + 16 < NN, od = r0 + 24 < NN;
        if (oa) *(float2*)&g_z2[(size_t)r0 * 128 + c]        = make_float2(v0, v1);
        if (ob) *(float2*)&g_z2[(size_t)(r0 + 8) * 128 + c]  = make_float2(v2, v3);
        if (oc) *(float2*)&g_z2[(size_t)(r0 + 16) * 128 + c] = make_float2(u0, u1);
        if (od) *(float2*)&g_z2[(size_t)(r0 + 24) * 128 + c] = make_float2(u2, u3);
        float s0 = 0.f, s1 = 0.f, q0 = 0.f, q1 = 0.f;
        if (oa) { s0 += v0; s1 += v1; q0 += v0 * v0; q1 += v1 * v1; }
        if (ob) { s0 += v2; s1 += v3; q0 += v2 * v2; q1 += v3 * v3; }
        if (oc) { s0 += u0; s1 += u1; q0 += u0 * u0; q1 += u1 * u1; }
        if (od) { s0 += u2; s1 += u3; q0 += u2 * u2; q1 += u3 * u3; }
        s[2 * nt] = s0; s[2 * nt + 1] = s1; q[2 * nt] = q0; q[2 * nt + 1] = q1;
    }
    #pragma unroll
    for (int off = 16; off >= 4; off >>= 1) {
        #pragma unroll
        for (int i = 0; i < 16; i++) {
            s[i] += __shfl_down_sync(0xffffffffu, s[i], off);
            q[i] += __shfl_down_sync(0xffffffffu, q[i], off);
        }
    }
    if (lane < 4) {
        #pragma unroll
        for (int nt = 0; nt < 8; nt++) {
            int c = colb + nt * 8 + 2 * lane;
            atomicAdd(&g_sum2[c], s[2 * nt]);
            atomicAdd(&g_sum2[c + 1], s[2 * nt + 1]);
            atomicAdd(&g_sq2[c], q[2 * nt]);
            atomicAdd(&g_sq2[c + 1], q[2 * nt + 1]);
        }
    }
}

// ===================== residual update (BN2 finalize fused; resets BN1 stats) =====================
__global__ void k_update(float* __restrict__ dout, int last, int relu,
                         const float* __restrict__ g, const float* __restrict__ beta) {
    __shared__ float s_sc[DD], s_sh[DD];
    int tid = threadIdx.x;
    if (tid < DD) {
        const float invN = 1.0f / (float)NN;
        float m = g_sum2[tid] * invN;
        float v = g_sq2[tid] * invN - m * m;
        float sc = g[tid] * rsqrtf(v + 1e-5f);
        s_sc[tid] = sc;
        s_sh[tid] = beta[tid] - m * sc;
    }
    if (blockIdx.x == 0 && tid < 2 * DD) { g_sum1[tid] = 0.f; g_sq1[tid] = 0.f; }
    __syncthreads();
    float* out = last ? dout : g_h;
    for (int i = blockIdx.x * blockDim.x + tid; i < NN * DD / 4; i += gridDim.x * blockDim.x) {
        int c4 = i & 31;
        float4 z = ((const float4*)g_z2)[i];
        float4 sc = ((const float4*)s_sc)[c4];
        float4 sh = ((const float4*)s_sh)[c4];
        float4 h = ((const float4*)g_h)[i];
        float vx = fmaf(z.x, sc.x, sh.x);
        float vy = fmaf(z.y, sc.y, sh.y);
        float vz = fmaf(z.z, sc.z, sh.z);
        float vw = fmaf(z.w, sc.w, sh.w);
        if (relu) {
            vx = fmaxf(vx, 0.f); vy = fmaxf(vy, 0.f);
            vz = fmaxf(vz, 0.f); vw = fmaxf(vw, 0.f);
        }
        ((float4*)out)[i] = make_float4(vx + h.x, vy + h.y, vz + h.z, vw + h.w);
    }
}

// ===================== host launcher =====================
extern "C" void kernel_launch(void* const* d_in, const int* in_sizes, int n_in,
                              void* d_out, int out_size) {
    const float* x       = (const float*)d_in[0];
    const int*   ei      = (const int*)d_in[1];
    const float* ea      = (const float*)d_in[2];
    const float* W_node  = (const float*)d_in[3];
    const float* b_node  = (const float*)d_in[4];
    const float* We      = (const float*)d_in[5];
    const float* be      = (const float*)d_in[6];
    const float* eps_gin = (const float*)d_in[7];
    const float* W1      = (const float*)d_in[8];
    const float* b1      = (const float*)d_in[9];
    const float* g1      = (const float*)d_in[10];
    const float* beta1   = (const float*)d_in[11];
    const float* W2      = (const float*)d_in[12];
    const float* b2      = (const float*)d_in[13];
    const float* g_bn    = (const float*)d_in[14];
    const float* beta_bn = (const float*)d_in[15];
    float* out = (float*)d_out;

    cudaFuncSetAttribute(k_gemm1, cudaFuncAttributeMaxDynamicSharedMemorySize, GEMM_SMEM);
    cudaFuncSetAttribute(k_gemm2, cudaFuncAttributeMaxDynamicSharedMemorySize, GEMM_SMEM);

    const int NB = (NN + 255) / 256;  // 196
    const int NT = (NN + 127) / 128;  // 391 row tiles

    k_init<<<NB, 256>>>();
    k_node_enc<<<1184, 256>>>(x, W_node, b_node);
    k_hist<<<EE / 256, 256>>>(ei);
    k_scanA<<<NB, 256>>>();
    k_scanB<<<1, 256>>>(NB);
    k_scanC<<<NB, 256>>>();
    k_scatter<<<EE / 256, 256>>>(ei);
    k_wconv<<<1280, 256>>>(W1, W2);

    for (int l = 0; l < LL; l++) {
        k_agg<<<2368, 256>>>(ea, We, be, eps_gin, l);
        k_gemm1<<<dim3(NT, 2), 256, GEMM_SMEM>>>(l, b1 + (size_t)l * 2 * DD);
        k_conv2<<<1184, 256>>>(g1 + (size_t)l * 2 * DD, beta1 + (size_t)l * 2 * DD);
        k_gemm2<<<NT, 256, GEMM_SMEM>>>(l, b2 + (size_t)l * DD);
        k_update<<<1184, 256>>>(out, (l == LL - 1) ? 1 : 0, (l < LL - 1) ? 1 : 0,
                                g_bn + (size_t)l * DD, beta_bn + (size_t)l * DD);
    }
}

// round 15
// speedup vs baseline: 1.4881x; 1.4881x over previous
#include <cuda_runtime.h>
#include <cuda_bf16.h>
#include <cstdint>

#define NN 50000
#define EE 800000
#define DD 128
#define FF 16
#define LL 5

typedef unsigned long long ull;
typedef unsigned short u16;

// ===================== fp32 packed-FMA helpers =====================
__device__ __forceinline__ ull ffma2(ull a, ull b, ull c) {
    ull d;
    asm("fma.rn.f32x2 %0,%1,%2,%3;" : "=l"(d) : "l"(a), "l"(b), "l"(c));
    return d;
}
__device__ __forceinline__ ull pack2(float lo, float hi) {
    ull r;
    asm("mov.b64 %0,{%1,%2};" : "=l"(r) : "f"(lo), "f"(hi));
    return r;
}
__device__ __forceinline__ void unpack2(ull v, float& lo, float& hi) {
    asm("mov.b64 {%0,%1},%2;" : "=f"(lo), "=f"(hi) : "l"(v));
}

__device__ __forceinline__ uint32_t smem_u32(const void* p) {
    uint32_t a;
    asm("{ .reg .u64 t; cvta.to.shared.u64 t, %1; cvt.u32.u64 %0, t; }" : "=r"(a) : "l"(p));
    return a;
}

// ===================== mma.sync helpers (baseline PTX) =====================
__device__ __forceinline__ void ldsm4(uint32_t* r, uint32_t addr) {
    asm volatile("ldmatrix.sync.aligned.m8n8.x4.shared.b16 {%0,%1,%2,%3}, [%4];"
                 : "=r"(r[0]), "=r"(r[1]), "=r"(r[2]), "=r"(r[3]) : "r"(addr));
}
__device__ __forceinline__ void mma_bf16(float* d, const uint32_t* a, const uint32_t* b) {
    asm volatile("mma.sync.aligned.m16n8k16.row.col.f32.bf16.bf16.f32 "
                 "{%0,%1,%2,%3},{%4,%5,%6,%7},{%8,%9},{%0,%1,%2,%3};"
                 : "+f"(d[0]), "+f"(d[1]), "+f"(d[2]), "+f"(d[3])
                 : "r"(a[0]), "r"(a[1]), "r"(a[2]), "r"(a[3]), "r"(b[0]), "r"(b[1]));
}

#define TSTRIDE 136
#define TILE_U16 (128 * TSTRIDE)
#define GEMM_SMEM (4 * TILE_U16 * 2)    // 139264 B dynamic (R7-proven layout)

// ===================== device scratch =====================
__device__ float g_h[NN * DD];
__device__ u16   g_z0h[NN * DD];
__device__ u16   g_z0l[NN * DD];
__device__ float g_t[NN * 2 * DD];
__device__ u16   g_t2h[NN * 2 * DD];
__device__ u16   g_t2l[NN * 2 * DD];
__device__ float g_z2[NN * DD];
__device__ u16   g_w1t_h[LL * 256 * 128], g_w1t_l[LL * 256 * 128];
__device__ u16   g_w2t_h[LL * 128 * 256], g_w2t_l[LL * 128 * 256];
__device__ int   g_cnt[NN];
__device__ int   g_rowptr[NN + 1];
__device__ int   g_fill[NN];
__device__ int2  g_sorted[EE];
__device__ int   g_part[200], g_partx[200];
__device__ float g_sum1[2 * DD], g_sq1[2 * DD];
__device__ float g_sum2[DD], g_sq2[DD];

// ===================== bf16 split helper =====================
__device__ __forceinline__ void split4(float a, float b, float c, float d, uint2& hi, uint2& lo) {
    __nv_bfloat16 h0 = __float2bfloat16(a), h1 = __float2bfloat16(b);
    __nv_bfloat16 h2 = __float2bfloat16(c), h3 = __float2bfloat16(d);
    __nv_bfloat16 l0 = __float2bfloat16(a - __bfloat162float(h0));
    __nv_bfloat16 l1 = __float2bfloat16(b - __bfloat162float(h1));
    __nv_bfloat16 l2 = __float2bfloat16(c - __bfloat162float(h2));
    __nv_bfloat16 l3 = __float2bfloat16(d - __bfloat162float(h3));
    hi.x = (uint32_t)__bfloat16_as_ushort(h0) | ((uint32_t)__bfloat16_as_ushort(h1) << 16);
    hi.y = (uint32_t)__bfloat16_as_ushort(h2) | ((uint32_t)__bfloat16_as_ushort(h3) << 16);
    lo.x = (uint32_t)__bfloat16_as_ushort(l0) | ((uint32_t)__bfloat16_as_ushort(l1) << 16);
    lo.y = (uint32_t)__bfloat16_as_ushort(l2) | ((uint32_t)__bfloat16_as_ushort(l3) << 16);
}

// ===================== init =====================
__global__ void k_init() {
    int i = blockIdx.x * blockDim.x + threadIdx.x;
    if (i < NN) g_cnt[i] = 0;
    if (i < 2 * DD) { g_sum1[i] = 0.f; g_sq1[i] = 0.f; }
    if (i < DD)     { g_sum2[i] = 0.f; g_sq2[i] = 0.f; }
}

// ===================== weight transpose + bf16 split =====================
__global__ void k_wconv(const float* __restrict__ W1, const float* __restrict__ W2) {
    int i = blockIdx.x * blockDim.x + threadIdx.x;
    if (i < LL * 32768) {
        int l = i >> 15, r = i & 32767, n = r >> 7, k = r & 127;
        float w = W1[(l << 15) + k * 256 + n];
        __nv_bfloat16 h = __float2bfloat16(w);
        __nv_bfloat16 lo = __float2bfloat16(w - __bfloat162float(h));
        g_w1t_h[i] = __bfloat16_as_ushort(h);
        g_w1t_l[i] = __bfloat16_as_ushort(lo);
    } else if (i < 2 * LL * 32768) {
        int j = i - LL * 32768;
        int l = j >> 15, r = j & 32767, n = r >> 8, k = r & 255;
        float w = W2[(l << 15) + k * 128 + n];
        __nv_bfloat16 h = __float2bfloat16(w);
        __nv_bfloat16 lo = __float2bfloat16(w - __bfloat162float(h));
        g_w2t_h[j] = __bfloat16_as_ushort(h);
        g_w2t_l[j] = __bfloat16_as_ushort(lo);
    }
}

// ===================== CSR build =====================
__global__ void k_hist(const int* __restrict__ ei) {
    int e = blockIdx.x * blockDim.x + threadIdx.x;
    if (e < EE) atomicAdd(&g_cnt[ei[EE + e]], 1);
}

__global__ void k_scanA() {
    __shared__ int red[8];
    int tid = threadIdx.x, lid = tid & 31, wid = tid >> 5;
    int i = blockIdx.x * 256 + tid;
    int v = (i < NN) ? g_cnt[i] : 0;
    #pragma unroll
    for (int o = 16; o >= 1; o >>= 1) v += __shfl_down_sync(0xffffffffu, v, o);
    if (lid == 0) red[wid] = v;
    __syncthreads();
    if (tid < 8) {
        int s = red[tid];
        #pragma unroll
        for (int o = 4; o >= 1; o >>= 1) s += __shfl_down_sync(0xffu, s, o);
        if (tid == 0) g_part[blockIdx.x] = s;
    }
}

__global__ void k_scanB(int nb) {
    __shared__ int ws[8];
    int tid = threadIdx.x, lid = tid & 31, wid = tid >> 5;
    int v = (tid < nb) ? g_part[tid] : 0;
    int x = v;
    #pragma unroll
    for (int o = 1; o < 32; o <<= 1) {
        int t = __shfl_up_sync(0xffffffffu, x, o);
        if (lid >= o) x += t;
    }
    if (lid == 31) ws[wid] = x;
    __syncthreads();
    if (wid == 0 && lid < 8) {
        int s = ws[lid], y = s;
        #pragma unroll
        for (int o = 1; o < 8; o <<= 1) {
            int t = __shfl_up_sync(0xffu, y, o);
            if (lid >= o) y += t;
        }
        ws[lid] = y - s;
    }
    __syncthreads();
    int excl = ws[wid] + x - v;
    if (tid < nb) g_partx[tid] = excl;
    if (tid == nb - 1) g_rowptr[NN] = excl + v;
}

__global__ void k_scanC() {
    __shared__ int ws[8];
    int tid = threadIdx.x, lid = tid & 31, wid = tid >> 5;
    int i = blockIdx.x * 256 + tid;
    int v = (i < NN) ? g_cnt[i] : 0;
    int x = v;
    #pragma unroll
    for (int o = 1; o < 32; o <<= 1) {
        int t = __shfl_up_sync(0xffffffffu, x, o);
        if (lid >= o) x += t;
    }
    if (lid == 31) ws[wid] = x;
    __syncthreads();
    if (wid == 0 && lid < 8) {
        int s = ws[lid], y = s;
        #pragma unroll
        for (int o = 1; o < 8; o <<= 1) {
            int t = __shfl_up_sync(0xffu, y, o);
            if (lid >= o) y += t;
        }
        ws[lid] = y - s;
    }
    __syncthreads();
    int excl = g_partx[blockIdx.x] + ws[wid] + x - v;
    if (i < NN) { g_rowptr[i] = excl; g_fill[i] = excl; }
}

__global__ void k_scatter(const int* __restrict__ ei) {
    int e = blockIdx.x * blockDim.x + threadIdx.x;
    if (e < EE) {
        int d = ei[EE + e];
        int pos = atomicAdd(&g_fill[d], 1);
        g_sorted[pos] = make_int2(ei[e], e);
    }
}

// ===================== node encoder =====================
__global__ void k_node_enc(const float* __restrict__ x, const float* __restrict__ Wn,
                           const float* __restrict__ bn) {
    __shared__ float Ws[FF * DD];
    for (int i = threadIdx.x; i < FF * DD; i += blockDim.x) Ws[i] = Wn[i];
    __syncthreads();
    int lane = threadIdx.x & 31;
    int warp = (blockIdx.x * blockDim.x + threadIdx.x) >> 5;
    int nw = (gridDim.x * blockDim.x) >> 5;
    int c0 = lane * 4;
    ull wp[8][4];
    #pragma unroll
    for (int j = 0; j < 8; j++)
        #pragma unroll
        for (int ci = 0; ci < 4; ci++)
            wp[j][ci] = pack2(Ws[(2 * j) * DD + c0 + ci], Ws[(2 * j + 1) * DD + c0 + ci]);
    ull bias2[4];
    #pragma unroll
    for (int ci = 0; ci < 4; ci++) bias2[ci] = pack2(bn[c0 + ci], 0.f);
    for (int n = warp; n < NN; n += nw) {
        const float4* xr = (const float4*)(x + (size_t)n * FF);
        float4 e0 = xr[0], e1 = xr[1], e2 = xr[2], e3 = xr[3];
        ull xp[8] = { pack2(e0.x, e0.y), pack2(e0.z, e0.w), pack2(e1.x, e1.y), pack2(e1.z, e1.w),
                      pack2(e2.x, e2.y), pack2(e2.z, e2.w), pack2(e3.x, e3.y), pack2(e3.z, e3.w) };
        ull a0 = bias2[0], a1 = bias2[1], a2 = bias2[2], a3 = bias2[3];
        #pragma unroll
        for (int j = 0; j < 8; j++) {
            a0 = ffma2(xp[j], wp[j][0], a0);
            a1 = ffma2(xp[j], wp[j][1], a1);
            a2 = ffma2(xp[j], wp[j][2], a2);
            a3 = ffma2(xp[j], wp[j][3], a3);
        }
        float l0, h0, l1, h1, l2, h2, l3, h3;
        unpack2(a0, l0, h0); unpack2(a1, l1, h1);
        unpack2(a2, l2, h2); unpack2(a3, l3, h3);
        *(float4*)&g_h[(size_t)n * DD + c0] = make_float4(l0 + h0, l1 + h1, l2 + h2, l3 + h3);
    }
}

// ===================== fused edge-encode + gather + aggregate (R3/R7-proven variant) =====================
// block 0 additionally resets g_sum2/g_sq2 for this layer's gemm2 (previous layer's
// k_update has already consumed them).
__global__ void k_agg(const float* __restrict__ ea, const float* __restrict__ We,
                      const float* __restrict__ be, const float* __restrict__ epsv, int layer) {
    __shared__ float Ws[FF * DD];
    for (int i = threadIdx.x; i < FF * DD; i += blockDim.x) Ws[i] = We[layer * FF * DD + i];
    if (blockIdx.x == 0 && threadIdx.x < DD) { g_sum2[threadIdx.x] = 0.f; g_sq2[threadIdx.x] = 0.f; }
    __syncthreads();
    int lane = threadIdx.x & 31;
    int warp = (blockIdx.x * blockDim.x + threadIdx.x) >> 5;
    int nw = (gridDim.x * blockDim.x) >> 5;
    int c0 = lane * 4;
    ull w01[FF], w23[FF];
    #pragma unroll
    for (int f = 0; f < FF; f++) {
        const ull* p = (const ull*)&Ws[f * DD + c0];
        w01[f] = p[0]; w23[f] = p[1];
    }
    ull b01 = *(const ull*)&be[layer * DD + c0];
    ull b23 = *(const ull*)&be[layer * DD + c0 + 2];
    float eps1 = 1.0f + epsv[layer];

    for (int n = warp; n < NN; n += nw) {
        int p0 = g_rowptr[n], p1 = g_rowptr[n + 1];
        float ax = 0.f, ay = 0.f, az = 0.f, aw = 0.f;
        int p = p0;
        for (; p + 1 < p1; p += 2) {
            int2 seA = g_sorted[p];
            int2 seB = g_sorted[p + 1];
            const float4* erA = (const float4*)(ea + (size_t)seA.y * FF);
            const float4* erB = (const float4*)(ea + (size_t)seB.y * FF);
            float xaA[16], xaB[16];
            *(float4*)&xaA[0] = erA[0]; *(float4*)&xaA[4] = erA[1];
            *(float4*)&xaA[8] = erA[2]; *(float4*)&xaA[12] = erA[3];
            *(float4*)&xaB[0] = erB[0]; *(float4*)&xaB[4] = erB[1];
            *(float4*)&xaB[8] = erB[2]; *(float4*)&xaB[12] = erB[3];
            float4 hvA = *(const float4*)&g_h[(size_t)seA.x * DD + c0];
            float4 hvB = *(const float4*)&g_h[(size_t)seB.x * DD + c0];
            ull mA01 = b01, mA23 = b23, mB01 = b01, mB23 = b23;
            #pragma unroll
            for (int f = 0; f < FF; f++) {
                ull xxA = pack2(xaA[f], xaA[f]);
                ull xxB = pack2(xaB[f], xaB[f]);
                mA01 = ffma2(xxA, w01[f], mA01);
                mA23 = ffma2(xxA, w23[f], mA23);
                mB01 = ffma2(xxB, w01[f], mB01);
                mB23 = ffma2(xxB, w23[f], mB23);
            }
            float a0, a1, a2, a3, b0, b1f, b2f, b3;
            unpack2(mA01, a0, a1); unpack2(mA23, a2, a3);
            unpack2(mB01, b0, b1f); unpack2(mB23, b2f, b3);
            ax += fmaxf(a0 + hvA.x, 0.f) + fmaxf(b0 + hvB.x, 0.f);
            ay += fmaxf(a1 + hvA.y, 0.f) + fmaxf(b1f + hvB.y, 0.f);
            az += fmaxf(a2 + hvA.z, 0.f) + fmaxf(b2f + hvB.z, 0.f);
            aw += fmaxf(a3 + hvA.w, 0.f) + fmaxf(b3 + hvB.w, 0.f);
        }
        if (p < p1) {
            int2 se = g_sorted[p];
            const float4* er = (const float4*)(ea + (size_t)se.y * FF);
            float xa[16];
            *(float4*)&xa[0] = er[0]; *(float4*)&xa[4] = er[1];
            *(float4*)&xa[8] = er[2]; *(float4*)&xa[12] = er[3];
            float4 hv = *(const float4*)&g_h[(size_t)se.x * DD + c0];
            ull m01 = b01, m23 = b23;
            #pragma unroll
            for (int f = 0; f < FF; f++) {
                ull xx = pack2(xa[f], xa[f]);
                m01 = ffma2(xx, w01[f], m01);
                m23 = ffma2(xx, w23[f], m23);
            }
            float m0, m1, m2, m3;
            unpack2(m01, m0, m1); unpack2(m23, m2, m3);
            ax += fmaxf(m0 + hv.x, 0.f);
            ay += fmaxf(m1 + hv.y, 0.f);
            az += fmaxf(m2 + hv.z, 0.f);
            aw += fmaxf(m3 + hv.w, 0.f);
        }
        float4 hs = *(const float4*)&g_h[(size_t)n * DD + c0];
        float o0 = fmaf(eps1, hs.x, ax), o1 = fmaf(eps1, hs.y, ay);
        float o2 = fmaf(eps1, hs.z, az), o3 = fmaf(eps1, hs.w, aw);
        uint2 hi, lo;
        split4(o0, o1, o2, o3, hi, lo);
        *(uint2*)&g_z0h[(size_t)n * DD + c0] = hi;
        *(uint2*)&g_z0l[(size_t)n * DD + c0] = lo;
    }
}

// ===================== stage 128x128 bf16 tile into padded smem (256 threads) =====================
__device__ __forceinline__ void stage_tile(u16* s, const uint4* src, int stride_u4,
                                           int off_u4, int vr, int tid) {
    #pragma unroll
    for (int j = 0; j < 8; j++) {
        int idx = tid + j * 256;
        int r = idx >> 4, q = idx & 15;
        uint4 v = make_uint4(0u, 0u, 0u, 0u);
        if (r < vr) v = src[(size_t)r * stride_u4 + off_u4 + q];
        *(uint4*)&s[r * TSTRIDE + q * 8] = v;
    }
}

// ===================== dual-A mma pass: (Ah·B + Al·B) with B fragments loaded ONCE =====================
__device__ __forceinline__ void gemm_pass_dual(uint32_t sAh, uint32_t sAl, uint32_t sB,
                                               int lane, int wm, int wn, float acc[2][8][4]) {
    uint32_t a_off = ((uint32_t)((wm * 32 + (lane & 15)) * TSTRIDE + ((lane >> 4) << 3)) << 1);
    uint32_t a_baseH = sAh + a_off;
    uint32_t a_baseL = sAl + a_off;
    int noff = (lane & 7) + ((lane & 16) >> 1);
    int koff = (lane & 8) ? 8 : 0;
    #pragma unroll
    for (int ks = 0; ks < 8; ks++) {
        int k0 = ks * 16;
        uint32_t bF[8][2];
        #pragma unroll
        for (int p = 0; p < 4; p++) {
            uint32_t r[4];
            uint32_t b_addr = sB + ((uint32_t)((wn * 64 + p * 16 + noff) * TSTRIDE + k0 + koff) << 1);
            ldsm4(r, b_addr);
            bF[2 * p][0] = r[0]; bF[2 * p][1] = r[1];
            bF[2 * p + 1][0] = r[2]; bF[2 * p + 1][1] = r[3];
        }
        uint32_t aH[2][4], aL[2][4];
        ldsm4(aH[0], a_baseH + (k0 << 1));
        ldsm4(aH[1], a_baseH + ((16 * TSTRIDE + k0) << 1));
        ldsm4(aL[0], a_baseL + (k0 << 1));
        ldsm4(aL[1], a_baseL + ((16 * TSTRIDE + k0) << 1));
        #pragma unroll
        for (int mt = 0; mt < 2; mt++)
            #pragma unroll
            for (int nt = 0; nt < 8; nt++)
                mma_bf16(acc[mt][nt], aH[mt], bF[nt]);
        #pragma unroll
        for (int mt = 0; mt < 2; mt++)
            #pragma unroll
            for (int nt = 0; nt < 8; nt++)
                mma_bf16(acc[mt][nt], aL[mt], bF[nt]);
    }
}

// ===================== single-A mma pass (Ah·Bl) =====================
__device__ __forceinline__ void gemm_pass(uint32_t sA, uint32_t sB, int lane, int wm, int wn,
                                          float acc[2][8][4]) {
    uint32_t a_base = sA + ((uint32_t)((wm * 32 + (lane & 15)) * TSTRIDE + ((lane >> 4) << 3)) << 1);
    int noff = (lane & 7) + ((lane & 16) >> 1);
    int koff = (lane & 8) ? 8 : 0;
    #pragma unroll
    for (int ks = 0; ks < 8; ks++) {
        int k0 = ks * 16;
        uint32_t aF[2][4];
        ldsm4(aF[0], a_base + (k0 << 1));
        ldsm4(aF[1], a_base + ((16 * TSTRIDE + k0) << 1));
        uint32_t bF[8][2];
        #pragma unroll
        for (int p = 0; p < 4; p++) {
            uint32_t r[4];
            uint32_t b_addr = sB + ((uint32_t)((wn * 64 + p * 16 + noff) * TSTRIDE + k0 + koff) << 1);
            ldsm4(r, b_addr);
            bF[2 * p][0] = r[0]; bF[2 * p][1] = r[1];
            bF[2 * p + 1][0] = r[2]; bF[2 * p + 1][1] = r[3];
        }
        #pragma unroll
        for (int mt = 0; mt < 2; mt++)
            #pragma unroll
            for (int nt = 0; nt < 8; nt++)
                mma_bf16(acc[mt][nt], aF[mt], bF[nt]);
    }
}

// ===================== GEMM1: t[N,256] = z0 @ W1 + b1 (+ column stats) =====================
__global__ void __launch_bounds__(256) k_gemm1(int layer, const float* __restrict__ b1) {
    extern __shared__ u16 sm[];
    u16* sAh = sm;
    u16* sAl = sAh + TILE_U16;
    u16* sBh = sAl + TILE_U16;
    u16* sBl = sBh + TILE_U16;
    int tid = threadIdx.x, lane = tid & 31, w = tid >> 5;
    int wm = w >> 1, wn = w & 1;
    int rbase = blockIdx.x * 128, nblk = blockIdx.y;
    int vr = NN - rbase; if (vr > 128) vr = 128;

    stage_tile(sAh, (const uint4*)(g_z0h + (size_t)rbase * DD), 16, 0, vr, tid);
    stage_tile(sAl, (const uint4*)(g_z0l + (size_t)rbase * DD), 16, 0, vr, tid);
    const uint4* Bh = (const uint4*)(g_w1t_h + (size_t)layer * 32768 + (size_t)nblk * 128 * 128);
    const uint4* Bl = (const uint4*)(g_w1t_l + (size_t)layer * 32768 + (size_t)nblk * 128 * 128);
    stage_tile(sBh, Bh, 16, 0, 128, tid);
    stage_tile(sBl, Bl, 16, 0, 128, tid);
    __syncthreads();

    float acc[2][8][4];
    #pragma unroll
    for (int mt = 0; mt < 2; mt++)
        #pragma unroll
        for (int nt = 0; nt < 8; nt++)
            #pragma unroll
            for (int i = 0; i < 4; i++) acc[mt][nt][i] = 0.f;

    uint32_t uAh = smem_u32(sAh), uAl = smem_u32(sAl);
    uint32_t uBh = smem_u32(sBh), uBl = smem_u32(sBl);
    gemm_pass_dual(uAh, uAl, uBh, lane, wm, wn, acc);
    gemm_pass(uAh, uBl, lane, wm, wn, acc);

    int colb = nblk * 128 + wn * 64;
    int r0 = rbase + wm * 32 + (lane >> 2);
    float s[16], q[16];
    #pragma unroll
    for (int nt = 0; nt < 8; nt++) {
        int c = colb + nt * 8 + 2 * (lane & 3);
        float bx = __ldg(&b1[c]), by = __ldg(&b1[c + 1]);
        float v0 = acc[0][nt][0] + bx, v1 = acc[0][nt][1] + by;
        float v2 = acc[0][nt][2] + bx, v3 = acc[0][nt][3] + by;
        float u0 = acc[1][nt][0] + bx, u1 = acc[1][nt][1] + by;
        float u2 = acc[1][nt][2] + bx, u3 = acc[1][nt][3] + by;
        bool oa = r0 < NN, ob = r0 + 8 < NN, oc = r0 + 16 < NN, od = r0 + 24 < NN;
        if (oa) *(float2*)&g_t[(size_t)r0 * 256 + c]        = make_float2(v0, v1);
        if (ob) *(float2*)&g_t[(size_t)(r0 + 8) * 256 + c]  = make_float2(v2, v3);
        if (oc) *(float2*)&g_t[(size_t)(r0 + 16) * 256 + c] = make_float2(u0, u1);
        if (od) *(float2*)&g_t[(size_t)(r0 + 24) * 256 + c] = make_float2(u2, u3);
        float s0 = 0.f, s1 = 0.f, q0 = 0.f, q1 = 0.f;
        if (oa) { s0 += v0; s1 += v1; q0 += v0 * v0; q1 += v1 * v1; }
        if (ob) { s0 += v2; s1 += v3; q0 += v2 * v2; q1 += v3 * v3; }
        if (oc) { s0 += u0; s1 += u1; q0 += u0 * u0; q1 += u1 * u1; }
        if (od) { s0 += u2; s1 += u3; q0 += u2 * u2; q1 += u3 * u3; }
        s[2 * nt] = s0; s[2 * nt + 1] = s1; q[2 * nt] = q0; q[2 * nt + 1] = q1;
    }
    #pragma unroll
    for (int off = 16; off >= 4; off >>= 1) {
        #pragma unroll
        for (int i = 0; i < 16; i++) {
            s[i] += __shfl_down_sync(0xffffffffu, s[i], off);
            q[i] += __shfl_down_sync(0xffffffffu, q[i], off);
        }
    }
    if (lane < 4) {
        #pragma unroll
        for (int nt = 0; nt < 8; nt++) {
            int c = colb + nt * 8 + 2 * lane;
            atomicAdd(&g_sum1[c], s[2 * nt]);
            atomicAdd(&g_sum1[c + 1], s[2 * nt + 1]);
            atomicAdd(&g_sq1[c], q[2 * nt]);
            atomicAdd(&g_sq1[c + 1], q[2 * nt + 1]);
        }
    }
}

// ===================== conv2 (BN1 finalize fused): t2 = relu(BN1(t)) as bf16 hi/lo =====================
__global__ void k_conv2(const float* __restrict__ g1, const float* __restrict__ beta1) {
    __shared__ float s_sc[2 * DD], s_sh[2 * DD];
    int tid = threadIdx.x;
    {
        const float invN = 1.0f / (float)NN;
        float m = g_sum1[tid] * invN;
        float v = g_sq1[tid] * invN - m * m;
        float sc = g1[tid] * rsqrtf(v + 1e-5f);
        s_sc[tid] = sc;
        s_sh[tid] = beta1[tid] - m * sc;
    }
    __syncthreads();
    for (int i = blockIdx.x * blockDim.x + tid; i < NN * 64; i += gridDim.x * blockDim.x) {
        int c4 = i & 63;
        float4 t = ((const float4*)g_t)[i];
        float4 sc = ((const float4*)s_sc)[c4];
        float4 sh = ((const float4*)s_sh)[c4];
        float v0 = fmaxf(fmaf(t.x, sc.x, sh.x), 0.f);
        float v1 = fmaxf(fmaf(t.y, sc.y, sh.y), 0.f);
        float v2 = fmaxf(fmaf(t.z, sc.z, sh.z), 0.f);
        float v3 = fmaxf(fmaf(t.w, sc.w, sh.w), 0.f);
        uint2 hi, lo;
        split4(v0, v1, v2, v3, hi, lo);
        ((uint2*)g_t2h)[i] = hi;
        ((uint2*)g_t2l)[i] = lo;
    }
}

// ===================== GEMM2: z2[N,128] = t2 @ W2 + b2 (K=256, 2 chunks; + stats) =====================
__global__ void __launch_bounds__(256) k_gemm2(int layer, const float* __restrict__ b2) {
    extern __shared__ u16 sm[];
    u16* sAh = sm;
    u16* sAl = sAh + TILE_U16;
    u16* sBh = sAl + TILE_U16;
    u16* sBl = sBh + TILE_U16;
    int tid = threadIdx.x, lane = tid & 31, w = tid >> 5;
    int wm = w >> 1, wn = w & 1;
    int rbase = blockIdx.x * 128;
    int vr = NN - rbase; if (vr > 128) vr = 128;

    const uint4* Ah = (const uint4*)(g_t2h + (size_t)rbase * 256);
    const uint4* Al = (const uint4*)(g_t2l + (size_t)rbase * 256);
    const uint4* Bh = (const uint4*)(g_w2t_h + (size_t)layer * 32768);
    const uint4* Bl = (const uint4*)(g_w2t_l + (size_t)layer * 32768);

    float acc[2][8][4];
    #pragma unroll
    for (int mt = 0; mt < 2; mt++)
        #pragma unroll
        for (int nt = 0; nt < 8; nt++)
            #pragma unroll
            for (int i = 0; i < 4; i++) acc[mt][nt][i] = 0.f;

    uint32_t uAh = smem_u32(sAh), uAl = smem_u32(sAl);
    uint32_t uBh = smem_u32(sBh), uBl = smem_u32(sBl);

    #pragma unroll
    for (int c = 0; c < 2; c++) {
        if (c) __syncthreads();
        stage_tile(sAh, Ah, 32, c * 16, vr, tid);
        stage_tile(sAl, Al, 32, c * 16, vr, tid);
        stage_tile(sBh, Bh, 32, c * 16, 128, tid);
        stage_tile(sBl, Bl, 32, c * 16, 128, tid);
        __syncthreads();
        gemm_pass_dual(uAh, uAl, uBh, lane, wm, wn, acc);
        gemm_pass(uAh, uBl, lane, wm, wn, acc);
    }

    int colb = wn * 64;
    int r0 = rbase + wm * 32 + (lane >> 2);
    float s[16], q[16];
    #pragma unroll
    for (int nt = 0; nt < 8; nt++) {
        int c = colb + nt * 8 + 2 * (lane & 3);
        float bx = __ldg(&b2[c]), by = __ldg(&b2[c + 1]);
        float v0 = acc[0][nt][0] + bx, v1 = acc[0][nt][1] + by;
        float v2 = acc[0][nt][2] + bx, v3 = acc[0][nt][3] + by;
        float u0 = acc[1][nt][0] + bx, u1 = acc[1][nt][1] + by;
        float u2 = acc[1][nt][2] + bx, u3 = acc[1][nt][3] + by;
        bool oa = r0 < NN, ob = r0 + 8 < NN, oc = r0 + 16 < NN, od = r0 + 24 < NN;
        if (oa) *(float2*)&g_z2[(size_t)r0 * 128 + c]        = make_float2(v0, v1);
        if (ob) *(float2*)&g_z2[(size_t)(r0 + 8) * 128 + c]  = make_float2(v2, v3);
        if (oc) *(float2*)&g_z2[(size_t)(r0 + 16) * 128 + c] = make_float2(u0, u1);
        if (od) *(float2*)&g_z2[(size_t)(r0 + 24) * 128 + c] = make_float2(u2, u3);
        float s0 = 0.f, s1 = 0.f, q0 = 0.f, q1 = 0.f;
        if (oa) { s0 += v0; s1 += v1; q0 += v0 * v0; q1 += v1 * v1; }
        if (ob) { s0 += v2; s1 += v3; q0 += v2 * v2; q1 += v3 * v3; }
        if (oc) { s0 += u0; s1 += u1; q0 += u0 * u0; q1 += u1 * u1; }
        if (od) { s0 += u2; s1 += u3; q0 += u2 * u2; q1 += u3 * u3; }
        s[2 * nt] = s0; s[2 * nt + 1] = s1; q[2 * nt] = q0; q[2 * nt + 1] = q1;
    }
    #pragma unroll
    for (int off = 16; off >= 4; off >>= 1) {
        #pragma unroll
        for (int i = 0; i < 16; i++) {
            s[i] += __shfl_down_sync(0xffffffffu, s[i], off);
            q[i] += __shfl_down_sync(0xffffffffu, q[i], off);
        }
    }
    if (lane < 4) {
        #pragma unroll
        for (int nt = 0; nt < 8; nt++) {
            int c = colb + nt * 8 + 2 * lane;
            atomicAdd(&g_sum2[c], s[2 * nt]);
            atomicAdd(&g_sum2[c + 1], s[2 * nt + 1]);
            atomicAdd(&g_sq2[c], q[2 * nt]);
            atomicAdd(&g_sq2[c + 1], q[2 * nt + 1]);
        }
    }
}

// ===================== residual update (BN2 finalize fused; resets BN1 stats) =====================
__global__ void k_update(float* __restrict__ dout, int last, int relu,
                         const float* __restrict__ g, const float* __restrict__ beta) {
    __shared__ float s_sc[DD], s_sh[DD];
    int tid = threadIdx.x;
    if (tid < DD) {
        const float invN = 1.0f / (float)NN;
        float m = g_sum2[tid] * invN;
        float v = g_sq2[tid] * invN - m * m;
        float sc = g[tid] * rsqrtf(v + 1e-5f);
        s_sc[tid] = sc;
        s_sh[tid] = beta[tid] - m * sc;
    }
    if (blockIdx.x == 0 && tid < 2 * DD) { g_sum1[tid] = 0.f; g_sq1[tid] = 0.f; }
    __syncthreads();
    float* out = last ? dout : g_h;
    for (int i = blockIdx.x * blockDim.x + tid; i < NN * DD / 4; i += gridDim.x * blockDim.x) {
        int c4 = i & 31;
        float4 z = ((const float4*)g_z2)[i];
        float4 sc = ((const float4*)s_sc)[c4];
        float4 sh = ((const float4*)s_sh)[c4];
        float4 h = ((const float4*)g_h)[i];
        float vx = fmaf(z.x, sc.x, sh.x);
        float vy = fmaf(z.y, sc.y, sh.y);
        float vz = fmaf(z.z, sc.z, sh.z);
        float vw = fmaf(z.w, sc.w, sh.w);
        if (relu) {
            vx = fmaxf(vx, 0.f); vy = fmaxf(vy, 0.f);
            vz = fmaxf(vz, 0.f); vw = fmaxf(vw, 0.f);
        }
        ((float4*)out)[i] = make_float4(vx + h.x, vy + h.y, vz + h.z, vw + h.w);
    }
}

// ===================== host launcher =====================
extern "C" void kernel_launch(void* const* d_in, const int* in_sizes, int n_in,
                              void* d_out, int out_size) {
    const float* x       = (const float*)d_in[0];
    const int*   ei      = (const int*)d_in[1];
    const float* ea      = (const float*)d_in[2];
    const float* W_node  = (const float*)d_in[3];
    const float* b_node  = (const float*)d_in[4];
    const float* We      = (const float*)d_in[5];
    const float* be      = (const float*)d_in[6];
    const float* eps_gin = (const float*)d_in[7];
    const float* W1      = (const float*)d_in[8];
    const float* b1      = (const float*)d_in[9];
    const float* g1      = (const float*)d_in[10];
    const float* beta1   = (const float*)d_in[11];
    const float* W2      = (const float*)d_in[12];
    const float* b2      = (const float*)d_in[13];
    const float* g_bn    = (const float*)d_in[14];
    const float* beta_bn = (const float*)d_in[15];
    float* out = (float*)d_out;

    cudaFuncSetAttribute(k_gemm1, cudaFuncAttributeMaxDynamicSharedMemorySize, GEMM_SMEM);
    cudaFuncSetAttribute(k_gemm2, cudaFuncAttributeMaxDynamicSharedMemorySize, GEMM_SMEM);

    const int NB = (NN + 255) / 256;  // 196
    const int NT = (NN + 127) / 128;  // 391 row tiles

    k_init<<<NB, 256>>>();
    k_node_enc<<<1184, 256>>>(x, W_node, b_node);
    k_hist<<<EE / 256, 256>>>(ei);
    k_scanA<<<NB, 256>>>();
    k_scanB<<<1, 256>>>(NB);
    k_scanC<<<NB, 256>>>();
    k_scatter<<<EE / 256, 256>>>(ei);
    k_wconv<<<1280, 256>>>(W1, W2);

    for (int l = 0; l < LL; l++) {
        k_agg<<<2368, 256>>>(ea, We, be, eps_gin, l);
        k_gemm1<<<dim3(NT, 2), 256, GEMM_SMEM>>>(l, b1 + (size_t)l * 2 * DD);
        k_conv2<<<1184, 256>>>(g1 + (size_t)l * 2 * DD, beta1 + (size_t)l * 2 * DD);
        k_gemm2<<<NT, 256, GEMM_SMEM>>>(l, b2 + (size_t)l * DD);
        k_update<<<1184, 256>>>(out, (l == LL - 1) ? 1 : 0, (l < LL - 1) ? 1 : 0,
                                g_bn + (size_t)l * DD, beta_bn + (size_t)l * DD);
    }
}

// round 16
// speedup vs baseline: 1.5580x; 1.0470x over previous
#include <cuda_runtime.h>
#include <cuda_bf16.h>
#include <cstdint>

#define NN 50000
#define EE 800000
#define DD 128
#define FF 16
#define LL 5

typedef unsigned long long ull;
typedef unsigned short u16;

// ===================== fp32 packed-FMA helpers =====================
__device__ __forceinline__ ull ffma2(ull a, ull b, ull c) {
    ull d;
    asm("fma.rn.f32x2 %0,%1,%2,%3;" : "=l"(d) : "l"(a), "l"(b), "l"(c));
    return d;
}
__device__ __forceinline__ ull pack2(float lo, float hi) {
    ull r;
    asm("mov.b64 %0,{%1,%2};" : "=l"(r) : "f"(lo), "f"(hi));
    return r;
}
__device__ __forceinline__ void unpack2(ull v, float& lo, float& hi) {
    asm("mov.b64 {%0,%1},%2;" : "=f"(lo), "=f"(hi) : "l"(v));
}

__device__ __forceinline__ uint32_t smem_u32(const void* p) {
    uint32_t a;
    asm("{ .reg .u64 t; cvta.to.shared.u64 t, %1; cvt.u32.u64 %0, t; }" : "=r"(a) : "l"(p));
    return a;
}

// ===================== mma.sync helpers (baseline PTX) =====================
__device__ __forceinline__ void ldsm4(uint32_t* r, uint32_t addr) {
    asm volatile("ldmatrix.sync.aligned.m8n8.x4.shared.b16 {%0,%1,%2,%3}, [%4];"
                 : "=r"(r[0]), "=r"(r[1]), "=r"(r[2]), "=r"(r[3]) : "r"(addr));
}
__device__ __forceinline__ void mma_bf16(float* d, const uint32_t* a, const uint32_t* b) {
    asm volatile("mma.sync.aligned.m16n8k16.row.col.f32.bf16.bf16.f32 "
                 "{%0,%1,%2,%3},{%4,%5,%6,%7},{%8,%9},{%0,%1,%2,%3};"
                 : "+f"(d[0]), "+f"(d[1]), "+f"(d[2]), "+f"(d[3])
                 : "r"(a[0]), "r"(a[1]), "r"(a[2]), "r"(a[3]), "r"(b[0]), "r"(b[1]));
}

#define TSTRIDE 136
#define TILE_U16 (128 * TSTRIDE)
#define GEMM_SMEM (4 * TILE_U16 * 2)    // 139264 B dynamic (R7-proven layout)

// ===================== device scratch =====================
__device__ float g_h[NN * DD];
__device__ u16   g_z0h[NN * DD];
__device__ u16   g_z0l[NN * DD];
__device__ float g_t[NN * 2 * DD];
__device__ u16   g_t2h[NN * 2 * DD];
__device__ u16   g_t2l[NN * 2 * DD];
__device__ float g_z2[NN * DD];
__device__ u16   g_w1t_h[LL * 256 * 128], g_w1t_l[LL * 256 * 128];
__device__ u16   g_w2t_h[LL * 128 * 256], g_w2t_l[LL * 128 * 256];
__device__ int   g_cnt[NN];
__device__ int   g_rowptr[NN + 1];
__device__ int   g_fill[NN];
__device__ int2  g_sorted[EE];
__device__ int   g_part[200], g_partx[200];
__device__ float g_sum1[2 * DD], g_sq1[2 * DD];
__device__ float g_sum2[DD], g_sq2[DD];

// ===================== bf16 split helper =====================
__device__ __forceinline__ void split4(float a, float b, float c, float d, uint2& hi, uint2& lo) {
    __nv_bfloat16 h0 = __float2bfloat16(a), h1 = __float2bfloat16(b);
    __nv_bfloat16 h2 = __float2bfloat16(c), h3 = __float2bfloat16(d);
    __nv_bfloat16 l0 = __float2bfloat16(a - __bfloat162float(h0));
    __nv_bfloat16 l1 = __float2bfloat16(b - __bfloat162float(h1));
    __nv_bfloat16 l2 = __float2bfloat16(c - __bfloat162float(h2));
    __nv_bfloat16 l3 = __float2bfloat16(d - __bfloat162float(h3));
    hi.x = (uint32_t)__bfloat16_as_ushort(h0) | ((uint32_t)__bfloat16_as_ushort(h1) << 16);
    hi.y = (uint32_t)__bfloat16_as_ushort(h2) | ((uint32_t)__bfloat16_as_ushort(h3) << 16);
    lo.x = (uint32_t)__bfloat16_as_ushort(l0) | ((uint32_t)__bfloat16_as_ushort(l1) << 16);
    lo.y = (uint32_t)__bfloat16_as_ushort(l2) | ((uint32_t)__bfloat16_as_ushort(l3) << 16);
}

// ===================== init =====================
__global__ void k_init() {
    int i = blockIdx.x * blockDim.x + threadIdx.x;
    if (i < NN) g_cnt[i] = 0;
    if (i < 2 * DD) { g_sum1[i] = 0.f; g_sq1[i] = 0.f; }
    if (i < DD)     { g_sum2[i] = 0.f; g_sq2[i] = 0.f; }
}

// ===================== weight transpose + bf16 split =====================
__global__ void k_wconv(const float* __restrict__ W1, const float* __restrict__ W2) {
    int i = blockIdx.x * blockDim.x + threadIdx.x;
    if (i < LL * 32768) {
        int l = i >> 15, r = i & 32767, n = r >> 7, k = r & 127;
        float w = W1[(l << 15) + k * 256 + n];
        __nv_bfloat16 h = __float2bfloat16(w);
        __nv_bfloat16 lo = __float2bfloat16(w - __bfloat162float(h));
        g_w1t_h[i] = __bfloat16_as_ushort(h);
        g_w1t_l[i] = __bfloat16_as_ushort(lo);
    } else if (i < 2 * LL * 32768) {
        int j = i - LL * 32768;
        int l = j >> 15, r = j & 32767, n = r >> 8, k = r & 255;
        float w = W2[(l << 15) + k * 128 + n];
        __nv_bfloat16 h = __float2bfloat16(w);
        __nv_bfloat16 lo = __float2bfloat16(w - __bfloat162float(h));
        g_w2t_h[j] = __bfloat16_as_ushort(h);
        g_w2t_l[j] = __bfloat16_as_ushort(lo);
    }
}

// ===================== CSR build =====================
__global__ void k_hist(const int* __restrict__ ei) {
    int e = blockIdx.x * blockDim.x + threadIdx.x;
    if (e < EE) atomicAdd(&g_cnt[ei[EE + e]], 1);
}

__global__ void k_scanA() {
    __shared__ int red[8];
    int tid = threadIdx.x, lid = tid & 31, wid = tid >> 5;
    int i = blockIdx.x * 256 + tid;
    int v = (i < NN) ? g_cnt[i] : 0;
    #pragma unroll
    for (int o = 16; o >= 1; o >>= 1) v += __shfl_down_sync(0xffffffffu, v, o);
    if (lid == 0) red[wid] = v;
    __syncthreads();
    if (tid < 8) {
        int s = red[tid];
        #pragma unroll
        for (int o = 4; o >= 1; o >>= 1) s += __shfl_down_sync(0xffu, s, o);
        if (tid == 0) g_part[blockIdx.x] = s;
    }
}

__global__ void k_scanB(int nb) {
    __shared__ int ws[8];
    int tid = threadIdx.x, lid = tid & 31, wid = tid >> 5;
    int v = (tid < nb) ? g_part[tid] : 0;
    int x = v;
    #pragma unroll
    for (int o = 1; o < 32; o <<= 1) {
        int t = __shfl_up_sync(0xffffffffu, x, o);
        if (lid >= o) x += t;
    }
    if (lid == 31) ws[wid] = x;
    __syncthreads();
    if (wid == 0 && lid < 8) {
        int s = ws[lid], y = s;
        #pragma unroll
        for (int o = 1; o < 8; o <<= 1) {
            int t = __shfl_up_sync(0xffu, y, o);
            if (lid >= o) y += t;
        }
        ws[lid] = y - s;
    }
    __syncthreads();
    int excl = ws[wid] + x - v;
    if (tid < nb) g_partx[tid] = excl;
    if (tid == nb - 1) g_rowptr[NN] = excl + v;
}

__global__ void k_scanC() {
    __shared__ int ws[8];
    int tid = threadIdx.x, lid = tid & 31, wid = tid >> 5;
    int i = blockIdx.x * 256 + tid;
    int v = (i < NN) ? g_cnt[i] : 0;
    int x = v;
    #pragma unroll
    for (int o = 1; o < 32; o <<= 1) {
        int t = __shfl_up_sync(0xffffffffu, x, o);
        if (lid >= o) x += t;
    }
    if (lid == 31) ws[wid] = x;
    __syncthreads();
    if (wid == 0 && lid < 8) {
        int s = ws[lid], y = s;
        #pragma unroll
        for (int o = 1; o < 8; o <<= 1) {
            int t = __shfl_up_sync(0xffu, y, o);
            if (lid >= o) y += t;
        }
        ws[lid] = y - s;
    }
    __syncthreads();
    int excl = g_partx[blockIdx.x] + ws[wid] + x - v;
    if (i < NN) { g_rowptr[i] = excl; g_fill[i] = excl; }
}

__global__ void k_scatter(const int* __restrict__ ei) {
    int e = blockIdx.x * blockDim.x + threadIdx.x;
    if (e < EE) {
        int d = ei[EE + e];
        int pos = atomicAdd(&g_fill[d], 1);
        g_sorted[pos] = make_int2(ei[e], e);
    }
}

// ===================== node encoder =====================
__global__ void k_node_enc(const float* __restrict__ x, const float* __restrict__ Wn,
                           const float* __restrict__ bn) {
    __shared__ float Ws[FF * DD];
    for (int i = threadIdx.x; i < FF * DD; i += blockDim.x) Ws[i] = Wn[i];
    __syncthreads();
    int lane = threadIdx.x & 31;
    int warp = (blockIdx.x * blockDim.x + threadIdx.x) >> 5;
    int nw = (gridDim.x * blockDim.x) >> 5;
    int c0 = lane * 4;
    ull wp[8][4];
    #pragma unroll
    for (int j = 0; j < 8; j++)
        #pragma unroll
        for (int ci = 0; ci < 4; ci++)
            wp[j][ci] = pack2(Ws[(2 * j) * DD + c0 + ci], Ws[(2 * j + 1) * DD + c0 + ci]);
    ull bias2[4];
    #pragma unroll
    for (int ci = 0; ci < 4; ci++) bias2[ci] = pack2(bn[c0 + ci], 0.f);
    for (int n = warp; n < NN; n += nw) {
        const float4* xr = (const float4*)(x + (size_t)n * FF);
        float4 e0 = xr[0], e1 = xr[1], e2 = xr[2], e3 = xr[3];
        ull xp[8] = { pack2(e0.x, e0.y), pack2(e0.z, e0.w), pack2(e1.x, e1.y), pack2(e1.z, e1.w),
                      pack2(e2.x, e2.y), pack2(e2.z, e2.w), pack2(e3.x, e3.y), pack2(e3.z, e3.w) };
        ull a0 = bias2[0], a1 = bias2[1], a2 = bias2[2], a3 = bias2[3];
        #pragma unroll
        for (int j = 0; j < 8; j++) {
            a0 = ffma2(xp[j], wp[j][0], a0);
            a1 = ffma2(xp[j], wp[j][1], a1);
            a2 = ffma2(xp[j], wp[j][2], a2);
            a3 = ffma2(xp[j], wp[j][3], a3);
        }
        float l0, h0, l1, h1, l2, h2, l3, h3;
        unpack2(a0, l0, h0); unpack2(a1, l1, h1);
        unpack2(a2, l2, h2); unpack2(a3, l3, h3);
        *(float4*)&g_h[(size_t)n * DD + c0] = make_float4(l0 + h0, l1 + h1, l2 + h2, l3 + h3);
    }
}

// ===================== fused edge-encode + gather + aggregate (R3/R13-proven variant) =====================
// Launched with a single-resident-wave grid (296 blocks): same total resident warps,
// same per-node summation order, ~8x fewer block prologues and no wave transitions.
// block 0 additionally resets g_sum2/g_sq2 for this layer's gemm2.
__global__ void k_agg(const float* __restrict__ ea, const float* __restrict__ We,
                      const float* __restrict__ be, const float* __restrict__ epsv, int layer) {
    __shared__ float Ws[FF * DD];
    for (int i = threadIdx.x; i < FF * DD; i += blockDim.x) Ws[i] = We[layer * FF * DD + i];
    if (blockIdx.x == 0 && threadIdx.x < DD) { g_sum2[threadIdx.x] = 0.f; g_sq2[threadIdx.x] = 0.f; }
    __syncthreads();
    int lane = threadIdx.x & 31;
    int warp = (blockIdx.x * blockDim.x + threadIdx.x) >> 5;
    int nw = (gridDim.x * blockDim.x) >> 5;
    int c0 = lane * 4;
    ull w01[FF], w23[FF];
    #pragma unroll
    for (int f = 0; f < FF; f++) {
        const ull* p = (const ull*)&Ws[f * DD + c0];
        w01[f] = p[0]; w23[f] = p[1];
    }
    ull b01 = *(const ull*)&be[layer * DD + c0];
    ull b23 = *(const ull*)&be[layer * DD + c0 + 2];
    float eps1 = 1.0f + epsv[layer];

    for (int n = warp; n < NN; n += nw) {
        int p0 = g_rowptr[n], p1 = g_rowptr[n + 1];
        float ax = 0.f, ay = 0.f, az = 0.f, aw = 0.f;
        int p = p0;
        for (; p + 1 < p1; p += 2) {
            int2 seA = g_sorted[p];
            int2 seB = g_sorted[p + 1];
            const float4* erA = (const float4*)(ea + (size_t)seA.y * FF);
            const float4* erB = (const float4*)(ea + (size_t)seB.y * FF);
            float xaA[16], xaB[16];
            *(float4*)&xaA[0] = erA[0]; *(float4*)&xaA[4] = erA[1];
            *(float4*)&xaA[8] = erA[2]; *(float4*)&xaA[12] = erA[3];
            *(float4*)&xaB[0] = erB[0]; *(float4*)&xaB[4] = erB[1];
            *(float4*)&xaB[8] = erB[2]; *(float4*)&xaB[12] = erB[3];
            float4 hvA = *(const float4*)&g_h[(size_t)seA.x * DD + c0];
            float4 hvB = *(const float4*)&g_h[(size_t)seB.x * DD + c0];
            ull mA01 = b01, mA23 = b23, mB01 = b01, mB23 = b23;
            #pragma unroll
            for (int f = 0; f < FF; f++) {
                ull xxA = pack2(xaA[f], xaA[f]);
                ull xxB = pack2(xaB[f], xaB[f]);
                mA01 = ffma2(xxA, w01[f], mA01);
                mA23 = ffma2(xxA, w23[f], mA23);
                mB01 = ffma2(xxB, w01[f], mB01);
                mB23 = ffma2(xxB, w23[f], mB23);
            }
            float a0, a1, a2, a3, b0, b1f, b2f, b3;
            unpack2(mA01, a0, a1); unpack2(mA23, a2, a3);
            unpack2(mB01, b0, b1f); unpack2(mB23, b2f, b3);
            ax += fmaxf(a0 + hvA.x, 0.f) + fmaxf(b0 + hvB.x, 0.f);
            ay += fmaxf(a1 + hvA.y, 0.f) + fmaxf(b1f + hvB.y, 0.f);
            az += fmaxf(a2 + hvA.z, 0.f) + fmaxf(b2f + hvB.z, 0.f);
            aw += fmaxf(a3 + hvA.w, 0.f) + fmaxf(b3 + hvB.w, 0.f);
        }
        if (p < p1) {
            int2 se = g_sorted[p];
            const float4* er = (const float4*)(ea + (size_t)se.y * FF);
            float xa[16];
            *(float4*)&xa[0] = er[0]; *(float4*)&xa[4] = er[1];
            *(float4*)&xa[8] = er[2]; *(float4*)&xa[12] = er[3];
            float4 hv = *(const float4*)&g_h[(size_t)se.x * DD + c0];
            ull m01 = b01, m23 = b23;
            #pragma unroll
            for (int f = 0; f < FF; f++) {
                ull xx = pack2(xa[f], xa[f]);
                m01 = ffma2(xx, w01[f], m01);
                m23 = ffma2(xx, w23[f], m23);
            }
            float m0, m1, m2, m3;
            unpack2(m01, m0, m1); unpack2(m23, m2, m3);
            ax += fmaxf(m0 + hv.x, 0.f);
            ay += fmaxf(m1 + hv.y, 0.f);
            az += fmaxf(m2 + hv.z, 0.f);
            aw += fmaxf(m3 + hv.w, 0.f);
        }
        float4 hs = *(const float4*)&g_h[(size_t)n * DD + c0];
        float o0 = fmaf(eps1, hs.x, ax), o1 = fmaf(eps1, hs.y, ay);
        float o2 = fmaf(eps1, hs.z, az), o3 = fmaf(eps1, hs.w, aw);
        uint2 hi, lo;
        split4(o0, o1, o2, o3, hi, lo);
        *(uint2*)&g_z0h[(size_t)n * DD + c0] = hi;
        *(uint2*)&g_z0l[(size_t)n * DD + c0] = lo;
    }
}

// ===================== stage 128x128 bf16 tile into padded smem (256 threads) =====================
__device__ __forceinline__ void stage_tile(u16* s, const uint4* src, int stride_u4,
                                           int off_u4, int vr, int tid) {
    #pragma unroll
    for (int j = 0; j < 8; j++) {
        int idx = tid + j * 256;
        int r = idx >> 4, q = idx & 15;
        uint4 v = make_uint4(0u, 0u, 0u, 0u);
        if (r < vr) v = src[(size_t)r * stride_u4 + off_u4 + q];
        *(uint4*)&s[r * TSTRIDE + q * 8] = v;
    }
}

// ===================== dual-A mma pass: (Ah·B + Al·B) with B fragments loaded ONCE =====================
__device__ __forceinline__ void gemm_pass_dual(uint32_t sAh, uint32_t sAl, uint32_t sB,
                                               int lane, int wm, int wn, float acc[2][8][4]) {
    uint32_t a_off = ((uint32_t)((wm * 32 + (lane & 15)) * TSTRIDE + ((lane >> 4) << 3)) << 1);
    uint32_t a_baseH = sAh + a_off;
    uint32_t a_baseL = sAl + a_off;
    int noff = (lane & 7) + ((lane & 16) >> 1);
    int koff = (lane & 8) ? 8 : 0;
    #pragma unroll
    for (int ks = 0; ks < 8; ks++) {
        int k0 = ks * 16;
        uint32_t bF[8][2];
        #pragma unroll
        for (int p = 0; p < 4; p++) {
            uint32_t r[4];
            uint32_t b_addr = sB + ((uint32_t)((wn * 64 + p * 16 + noff) * TSTRIDE + k0 + koff) << 1);
            ldsm4(r, b_addr);
            bF[2 * p][0] = r[0]; bF[2 * p][1] = r[1];
            bF[2 * p + 1][0] = r[2]; bF[2 * p + 1][1] = r[3];
        }
        uint32_t aH[2][4], aL[2][4];
        ldsm4(aH[0], a_baseH + (k0 << 1));
        ldsm4(aH[1], a_baseH + ((16 * TSTRIDE + k0) << 1));
        ldsm4(aL[0], a_baseL + (k0 << 1));
        ldsm4(aL[1], a_baseL + ((16 * TSTRIDE + k0) << 1));
        #pragma unroll
        for (int mt = 0; mt < 2; mt++)
            #pragma unroll
            for (int nt = 0; nt < 8; nt++)
                mma_bf16(acc[mt][nt], aH[mt], bF[nt]);
        #pragma unroll
        for (int mt = 0; mt < 2; mt++)
            #pragma unroll
            for (int nt = 0; nt < 8; nt++)
                mma_bf16(acc[mt][nt], aL[mt], bF[nt]);
    }
}

// ===================== single-A mma pass (Ah·Bl) =====================
__device__ __forceinline__ void gemm_pass(uint32_t sA, uint32_t sB, int lane, int wm, int wn,
                                          float acc[2][8][4]) {
    uint32_t a_base = sA + ((uint32_t)((wm * 32 + (lane & 15)) * TSTRIDE + ((lane >> 4) << 3)) << 1);
    int noff = (lane & 7) + ((lane & 16) >> 1);
    int koff = (lane & 8) ? 8 : 0;
    #pragma unroll
    for (int ks = 0; ks < 8; ks++) {
        int k0 = ks * 16;
        uint32_t aF[2][4];
        ldsm4(aF[0], a_base + (k0 << 1));
        ldsm4(aF[1], a_base + ((16 * TSTRIDE + k0) << 1));
        uint32_t bF[8][2];
        #pragma unroll
        for (int p = 0; p < 4; p++) {
            uint32_t r[4];
            uint32_t b_addr = sB + ((uint32_t)((wn * 64 + p * 16 + noff) * TSTRIDE + k0 + koff) << 1);
            ldsm4(r, b_addr);
            bF[2 * p][0] = r[0]; bF[2 * p][1] = r[1];
            bF[2 * p + 1][0] = r[2]; bF[2 * p + 1][1] = r[3];
        }
        #pragma unroll
        for (int mt = 0; mt < 2; mt++)
            #pragma unroll
            for (int nt = 0; nt < 8; nt++)
                mma_bf16(acc[mt][nt], aF[mt], bF[nt]);
    }
}

// ===================== GEMM1: t[N,256] = z0 @ W1 + b1 (+ column stats) =====================
__global__ void __launch_bounds__(256) k_gemm1(int layer, const float* __restrict__ b1) {
    extern __shared__ u16 sm[];
    u16* sAh = sm;
    u16* sAl = sAh + TILE_U16;
    u16* sBh = sAl + TILE_U16;
    u16* sBl = sBh + TILE_U16;
    int tid = threadIdx.x, lane = tid & 31, w = tid >> 5;
    int wm = w >> 1, wn = w & 1;
    int rbase = blockIdx.x * 128, nblk = blockIdx.y;
    int vr = NN - rbase; if (vr > 128) vr = 128;

    stage_tile(sAh, (const uint4*)(g_z0h + (size_t)rbase * DD), 16, 0, vr, tid);
    stage_tile(sAl, (const uint4*)(g_z0l + (size_t)rbase * DD), 16, 0, vr, tid);
    const uint4* Bh = (const uint4*)(g_w1t_h + (size_t)layer * 32768 + (size_t)nblk * 128 * 128);
    const uint4* Bl = (const uint4*)(g_w1t_l + (size_t)layer * 32768 + (size_t)nblk * 128 * 128);
    stage_tile(sBh, Bh, 16, 0, 128, tid);
    stage_tile(sBl, Bl, 16, 0, 128, tid);
    __syncthreads();

    float acc[2][8][4];
    #pragma unroll
    for (int mt = 0; mt < 2; mt++)
        #pragma unroll
        for (int nt = 0; nt < 8; nt++)
            #pragma unroll
            for (int i = 0; i < 4; i++) acc[mt][nt][i] = 0.f;

    uint32_t uAh = smem_u32(sAh), uAl = smem_u32(sAl);
    uint32_t uBh = smem_u32(sBh), uBl = smem_u32(sBl);
    gemm_pass_dual(uAh, uAl, uBh, lane, wm, wn, acc);
    gemm_pass(uAh, uBl, lane, wm, wn, acc);

    int colb = nblk * 128 + wn * 64;
    int r0 = rbase + wm * 32 + (lane >> 2);
    float s[16], q[16];
    #pragma unroll
    for (int nt = 0; nt < 8; nt++) {
        int c = colb + nt * 8 + 2 * (lane & 3);
        float bx = __ldg(&b1[c]), by = __ldg(&b1[c + 1]);
        float v0 = acc[0][nt][0] + bx, v1 = acc[0][nt][1] + by;
        float v2 = acc[0][nt][2] + bx, v3 = acc[0][nt][3] + by;
        float u0 = acc[1][nt][0] + bx, u1 = acc[1][nt][1] + by;
        float u2 = acc[1][nt][2] + bx, u3 = acc[1][nt][3] + by;
        bool oa = r0 < NN, ob = r0 + 8 < NN, oc = r0 + 16 < NN, od = r0 + 24 < NN;
        if (oa) *(float2*)&g_t[(size_t)r0 * 256 + c]        = make_float2(v0, v1);
        if (ob) *(float2*)&g_t[(size_t)(r0 + 8) * 256 + c]  = make_float2(v2, v3);
        if (oc) *(float2*)&g_t[(size_t)(r0 + 16) * 256 + c] = make_float2(u0, u1);
        if (od) *(float2*)&g_t[(size_t)(r0 + 24) * 256 + c] = make_float2(u2, u3);
        float s0 = 0.f, s1 = 0.f, q0 = 0.f, q1 = 0.f;
        if (oa) { s0 += v0; s1 += v1; q0 += v0 * v0; q1 += v1 * v1; }
        if (ob) { s0 += v2; s1 += v3; q0 += v2 * v2; q1 += v3 * v3; }
        if (oc) { s0 += u0; s1 += u1; q0 += u0 * u0; q1 += u1 * u1; }
        if (od) { s0 += u2; s1 += u3; q0 += u2 * u2; q1 += u3 * u3; }
        s[2 * nt] = s0; s[2 * nt + 1] = s1; q[2 * nt] = q0; q[2 * nt + 1] = q1;
    }
    #pragma unroll
    for (int off = 16; off >= 4; off >>= 1) {
        #pragma unroll
        for (int i = 0; i < 16; i++) {
            s[i] += __shfl_down_sync(0xffffffffu, s[i], off);
            q[i] += __shfl_down_sync(0xffffffffu, q[i], off);
        }
    }
    if (lane < 4) {
        #pragma unroll
        for (int nt = 0; nt < 8; nt++) {
            int c = colb + nt * 8 + 2 * lane;
            atomicAdd(&g_sum1[c], s[2 * nt]);
            atomicAdd(&g_sum1[c + 1], s[2 * nt + 1]);
            atomicAdd(&g_sq1[c], q[2 * nt]);
            atomicAdd(&g_sq1[c + 1], q[2 * nt + 1]);
        }
    }
}

// ===================== conv2 (BN1 finalize fused): t2 = relu(BN1(t)) as bf16 hi/lo =====================
__global__ void k_conv2(const float* __restrict__ g1, const float* __restrict__ beta1) {
    __shared__ float s_sc[2 * DD], s_sh[2 * DD];
    int tid = threadIdx.x;
    {
        const float invN = 1.0f / (float)NN;
        float m = g_sum1[tid] * invN;
        float v = g_sq1[tid] * invN - m * m;
        float sc = g1[tid] * rsqrtf(v + 1e-5f);
        s_sc[tid] = sc;
        s_sh[tid] = beta1[tid] - m * sc;
    }
    __syncthreads();
    for (int i = blockIdx.x * blockDim.x + tid; i < NN * 64; i += gridDim.x * blockDim.x) {
        int c4 = i & 63;
        float4 t = ((const float4*)g_t)[i];
        float4 sc = ((const float4*)s_sc)[c4];
        float4 sh = ((const float4*)s_sh)[c4];
        float v0 = fmaxf(fmaf(t.x, sc.x, sh.x), 0.f);
        float v1 = fmaxf(fmaf(t.y, sc.y, sh.y), 0.f);
        float v2 = fmaxf(fmaf(t.z, sc.z, sh.z), 0.f);
        float v3 = fmaxf(fmaf(t.w, sc.w, sh.w), 0.f);
        uint2 hi, lo;
        split4(v0, v1, v2, v3, hi, lo);
        ((uint2*)g_t2h)[i] = hi;
        ((uint2*)g_t2l)[i] = lo;
    }
}

// ===================== GEMM2: z2[N,128] = t2 @ W2 + b2 (K=256, 2 chunks; + stats) =====================
__global__ void __launch_bounds__(256) k_gemm2(int layer, const float* __restrict__ b2) {
    extern __shared__ u16 sm[];
    u16* sAh = sm;
    u16* sAl = sAh + TILE_U16;
    u16* sBh = sAl + TILE_U16;
    u16* sBl = sBh + TILE_U16;
    int tid = threadIdx.x, lane = tid & 31, w = tid >> 5;
    int wm = w >> 1, wn = w & 1;
    int rbase = blockIdx.x * 128;
    int vr = NN - rbase; if (vr > 128) vr = 128;

    const uint4* Ah = (const uint4*)(g_t2h + (size_t)rbase * 256);
    const uint4* Al = (const uint4*)(g_t2l + (size_t)rbase * 256);
    const uint4* Bh = (const uint4*)(g_w2t_h + (size_t)layer * 32768);
    const uint4* Bl = (const uint4*)(g_w2t_l + (size_t)layer * 32768);

    float acc[2][8][4];
    #pragma unroll
    for (int mt = 0; mt < 2; mt++)
        #pragma unroll
        for (int nt = 0; nt < 8; nt++)
            #pragma unroll
            for (int i = 0; i < 4; i++) acc[mt][nt][i] = 0.f;

    uint32_t uAh = smem_u32(sAh), uAl = smem_u32(sAl);
    uint32_t uBh = smem_u32(sBh), uBl = smem_u32(sBl);

    #pragma unroll
    for (int c = 0; c < 2; c++) {
        if (c) __syncthreads();
        stage_tile(sAh, Ah, 32, c * 16, vr, tid);
        stage_tile(sAl, Al, 32, c * 16, vr, tid);
        stage_tile(sBh, Bh, 32, c * 16, 128, tid);
        stage_tile(sBl, Bl, 32, c * 16, 128, tid);
        __syncthreads();
        gemm_pass_dual(uAh, uAl, uBh, lane, wm, wn, acc);
        gemm_pass(uAh, uBl, lane, wm, wn, acc);
    }

    int colb = wn * 64;
    int r0 = rbase + wm * 32 + (lane >> 2);
    float s[16], q[16];
    #pragma unroll
    for (int nt = 0; nt < 8; nt++) {
        int c = colb + nt * 8 + 2 * (lane & 3);
        float bx = __ldg(&b2[c]), by = __ldg(&b2[c + 1]);
        float v0 = acc[0][nt][0] + bx, v1 = acc[0][nt][1] + by;
        float v2 = acc[0][nt][2] + bx, v3 = acc[0][nt][3] + by;
        float u0 = acc[1][nt][0] + bx, u1 = acc[1][nt][1] + by;
        float u2 = acc[1][nt][2] + bx, u3 = acc[1][nt][3] + by;
        bool oa = r0 < NN, ob = r0 + 8 < NN, oc = r0 + 16 < NN, od = r0 + 24 < NN;
        if (oa) *(float2*)&g_z2[(size_t)r0 * 128 + c]        = make_float2(v0, v1);
        if (ob) *(float2*)&g_z2[(size_t)(r0 + 8) * 128 + c]  = make_float2(v2, v3);
        if (oc) *(float2*)&g_z2[(size_t)(r0 + 16) * 128 + c] = make_float2(u0, u1);
        if (od) *(float2*)&g_z2[(size_t)(r0 + 24) * 128 + c] = make_float2(u2, u3);
        float s0 = 0.f, s1 = 0.f, q0 = 0.f, q1 = 0.f;
        if (oa) { s0 += v0; s1 += v1; q0 += v0 * v0; q1 += v1 * v1; }
        if (ob) { s0 += v2; s1 += v3; q0 += v2 * v2; q1 += v3 * v3; }
        if (oc) { s0 += u0; s1 += u1; q0 += u0 * u0; q1 += u1 * u1; }
        if (od) { s0 += u2; s1 += u3; q0 += u2 * u2; q1 += u3 * u3; }
        s[2 * nt] = s0; s[2 * nt + 1] = s1; q[2 * nt] = q0; q[2 * nt + 1] = q1;
    }
    #pragma unroll
    for (int off = 16; off >= 4; off >>= 1) {
        #pragma unroll
        for (int i = 0; i < 16; i++) {
            s[i] += __shfl_down_sync(0xffffffffu, s[i], off);
            q[i] += __shfl_down_sync(0xffffffffu, q[i], off);
        }
    }
    if (lane < 4) {
        #pragma unroll
        for (int nt = 0; nt < 8; nt++) {
            int c = colb + nt * 8 + 2 * lane;
            atomicAdd(&g_sum2[c], s[2 * nt]);
            atomicAdd(&g_sum2[c + 1], s[2 * nt + 1]);
            atomicAdd(&g_sq2[c], q[2 * nt]);
            atomicAdd(&g_sq2[c + 1], q[2 * nt + 1]);
        }
    }
}

// ===================== residual update (BN2 finalize fused; resets BN1 stats) =====================
__global__ void k_update(float* __restrict__ dout, int last, int relu,
                         const float* __restrict__ g, const float* __restrict__ beta) {
    __shared__ float s_sc[DD], s_sh[DD];
    int tid = threadIdx.x;
    if (tid < DD) {
        const float invN = 1.0f / (float)NN;
        float m = g_sum2[tid] * invN;
        float v = g_sq2[tid] * invN - m * m;
        float sc = g[tid] * rsqrtf(v + 1e-5f);
        s_sc[tid] = sc;
        s_sh[tid] = beta[tid] - m * sc;
    }
    if (blockIdx.x == 0 && tid < 2 * DD) { g_sum1[tid] = 0.f; g_sq1[tid] = 0.f; }
    __syncthreads();
    float* out = last ? dout : g_h;
    for (int i = blockIdx.x * blockDim.x + tid; i < NN * DD / 4; i += gridDim.x * blockDim.x) {
        int c4 = i & 31;
        float4 z = ((const float4*)g_z2)[i];
        float4 sc = ((const float4*)s_sc)[c4];
        float4 sh = ((const float4*)s_sh)[c4];
        float4 h = ((const float4*)g_h)[i];
        float vx = fmaf(z.x, sc.x, sh.x);
        float vy = fmaf(z.y, sc.y, sh.y);
        float vz = fmaf(z.z, sc.z, sh.z);
        float vw = fmaf(z.w, sc.w, sh.w);
        if (relu) {
            vx = fmaxf(vx, 0.f); vy = fmaxf(vy, 0.f);
            vz = fmaxf(vz, 0.f); vw = fmaxf(vw, 0.f);
        }
        ((float4*)out)[i] = make_float4(vx + h.x, vy + h.y, vz + h.z, vw + h.w);
    }
}

// ===================== host launcher =====================
extern "C" void kernel_launch(void* const* d_in, const int* in_sizes, int n_in,
                              void* d_out, int out_size) {
    const float* x       = (const float*)d_in[0];
    const int*   ei      = (const int*)d_in[1];
    const float* ea      = (const float*)d_in[2];
    const float* W_node  = (const float*)d_in[3];
    const float* b_node  = (const float*)d_in[4];
    const float* We      = (const float*)d_in[5];
    const float* be      = (const float*)d_in[6];
    const float* eps_gin = (const float*)d_in[7];
    const float* W1      = (const float*)d_in[8];
    const float* b1      = (const float*)d_in[9];
    const float* g1      = (const float*)d_in[10];
    const float* beta1   = (const float*)d_in[11];
    const float* W2      = (const float*)d_in[12];
    const float* b2      = (const float*)d_in[13];
    const float* g_bn    = (const float*)d_in[14];
    const float* beta_bn = (const float*)d_in[15];
    float* out = (float*)d_out;

    cudaFuncSetAttribute(k_gemm1, cudaFuncAttributeMaxDynamicSharedMemorySize, GEMM_SMEM);
    cudaFuncSetAttribute(k_gemm2, cudaFuncAttributeMaxDynamicSharedMemorySize, GEMM_SMEM);

    const int NB = (NN + 255) / 256;  // 196
    const int NT = (NN + 127) / 128;  // 391 row tiles

    k_init<<<NB, 256>>>();
    k_node_enc<<<1184, 256>>>(x, W_node, b_node);
    k_hist<<<EE / 256, 256>>>(ei);
    k_scanA<<<NB, 256>>>();
    k_scanB<<<1, 256>>>(NB);
    k_scanC<<<NB, 256>>>();
    k_scatter<<<EE / 256, 256>>>(ei);
    k_wconv<<<1280, 256>>>(W1, W2);

    for (int l = 0; l < LL; l++) {
        k_agg<<<296, 256>>>(ea, We, be, eps_gin, l);   // single-resident-wave grid
        k_gemm1<<<dim3(NT, 2), 256, GEMM_SMEM>>>(l, b1 + (size_t)l * 2 * DD);
        k_conv2<<<1184, 256>>>(g1 + (size_t)l * 2 * DD, beta1 + (size_t)l * 2 * DD);
        k_gemm2<<<NT, 256, GEMM_SMEM>>>(l, b2 + (size_t)l * DD);
        k_update<<<1184, 256>>>(out, (l == LL - 1) ? 1 : 0, (l < LL - 1) ? 1 : 0,
                                g_bn + (size_t)l * DD, beta_bn + (size_t)l * DD);
    }
}